// round 1
// baseline (speedup 1.0000x reference)
#include <cuda_runtime.h>
#include <math.h>

#define B_   64
#define S_   800
#define ENC_ 512
#define T_   250
#define V_   30
#define E_   512
#define H_   512
#define D_   256
#define P_   256

// ---------------- scratch (device globals; no allocation allowed) ----------
__device__ float g_key[B_*S_*P_];     // key_proj  (B,S,P)
__device__ float g_val[B_*S_*P_];     // val_proj  (B,S,P)
__device__ float g_embg[V_*4*H_];     // embed_W @ W_ih1[0:512] + b_ih1 + b_hh1
__device__ float g_h1[2][B_*H_];
__device__ float g_c1[B_*H_];
__device__ float g_h2[2][B_*D_];
__device__ float g_c2[B_*D_];
__device__ float g_ctx[B_*P_];

__device__ __forceinline__ float sigf(float x) { return 1.0f / (1.0f + expf(-x)); }

// ---------------- P1: key/val projection GEMM ------------------------------
// C(51200 x 512) = enc(51200 x 512) @ [Wk | Wv](512 x 512) + [bk | bv]
// 32x32 block tile, 2x2 micro tile, BK=16.
__global__ void kv_proj_kernel(const float* __restrict__ enc,
                               const float* __restrict__ Wk, const float* __restrict__ bk,
                               const float* __restrict__ Wv, const float* __restrict__ bv) {
    __shared__ float As[32][17];
    __shared__ float Bs[16][33];
    int m0 = blockIdx.y * 32;
    int n0 = blockIdx.x * 32;
    int tid = threadIdx.x;
    int tx = tid & 15, ty = tid >> 4;
    float acc00 = 0.f, acc01 = 0.f, acc10 = 0.f, acc11 = 0.f;
    for (int k0 = 0; k0 < ENC_; k0 += 16) {
        #pragma unroll
        for (int e = tid; e < 32 * 16; e += 256) {
            int r = e >> 4, kk = e & 15;
            As[r][kk] = enc[(m0 + r) * ENC_ + k0 + kk];
        }
        #pragma unroll
        for (int e = tid; e < 16 * 32; e += 256) {
            int kk = e >> 5, nn = e & 31;
            int n = n0 + nn;
            Bs[kk][nn] = (n < P_) ? Wk[(k0 + kk) * P_ + n] : Wv[(k0 + kk) * P_ + (n - P_)];
        }
        __syncthreads();
        #pragma unroll
        for (int kk = 0; kk < 16; kk++) {
            float a0 = As[ty * 2][kk], a1 = As[ty * 2 + 1][kk];
            float b0 = Bs[kk][tx * 2], b1 = Bs[kk][tx * 2 + 1];
            acc00 += a0 * b0; acc01 += a0 * b1;
            acc10 += a1 * b0; acc11 += a1 * b1;
        }
        __syncthreads();
    }
    #pragma unroll
    for (int i = 0; i < 2; i++) {
        int r = m0 + ty * 2 + i;
        #pragma unroll
        for (int jj = 0; jj < 2; jj++) {
            int n = n0 + tx * 2 + jj;
            float v = (i == 0) ? (jj == 0 ? acc00 : acc01) : (jj == 0 ? acc10 : acc11);
            if (n < P_) g_key[r * P_ + n] = v + bk[n];
            else        g_val[r * P_ + (n - P_)] = v + bv[n - P_];
        }
    }
}

// ---------------- P2: embedding -> LSTM1 gate precompute -------------------
// g_embg[v][g] = sum_e embW[v][e]*W_ih1[e][g] + b_ih1[g] + b_hh1[g]
__global__ void embg_kernel(const float* __restrict__ embW, const float* __restrict__ Wih1,
                            const float* __restrict__ bih1, const float* __restrict__ bhh1) {
    __shared__ float es[E_];
    int v = blockIdx.y;
    int g = blockIdx.x * 256 + threadIdx.x;
    for (int e = threadIdx.x; e < E_; e += 256) es[e] = embW[v * E_ + e];
    __syncthreads();
    float acc = bih1[g] + bhh1[g];
    #pragma unroll 4
    for (int e = 0; e < E_; e++) acc += es[e] * Wih1[e * (4 * H_) + g];
    g_embg[v * (4 * H_) + g] = acc;
}

// ---------------- P3: state init --------------------------------------------
__global__ void init_kernel() {
    int i = blockIdx.x * 256 + threadIdx.x;   // grid 128*256 = 32768 = B*H
    g_h1[0][i] = 0.f; g_h1[1][i] = 0.f; g_c1[i] = 0.f;
    if (i < B_ * D_) { g_h2[0][i] = 0.f; g_h2[1][i] = 0.f; g_c2[i] = 0.f; }
    if (i < B_ * P_) {
        int b = i / P_, p = i % P_;
        g_ctx[i] = g_key[(b * S_ + 0) * P_ + p];   // context init = key_proj[:,0,:]
    }
}

// ---------------- K1: LSTM1 --------------------------------------------------
// gates[b][col] = emb_gates[tok][col] + ctx[b]@W_ih1[512:768] + h1[b]@W_hh1
// block j owns hidden units j*4 .. j*4+3 (all 4 gate types), 128 blocks.
__global__ void lstm1_kernel(const float* __restrict__ Wih1, const float* __restrict__ Whh1,
                             const int* __restrict__ y, int t, int pp) {
    __shared__ float xs[64][17];
    __shared__ float ws[16][17];
    __shared__ float gsm[64][17];
    int j = blockIdx.x;
    int tid = threadIdx.x;
    int tx = tid & 7, ty = tid >> 3;       // 8 col-pairs x 32 batch-pairs
    float acc[2][2];
    {
        #pragma unroll
        for (int i = 0; i < 2; i++) {
            int b = ty * 2 + i;
            int tok = (t == 0) ? 0 : y[b * T_ + (t - 1)];
            #pragma unroll
            for (int jj = 0; jj < 2; jj++) {
                int q = tx * 2 + jj;
                int col = (q >> 2) * H_ + j * 4 + (q & 3);
                acc[i][jj] = g_embg[tok * (4 * H_) + col];
            }
        }
    }
    const float* __restrict__ h1old = g_h1[pp];
    for (int k0 = 0; k0 < P_ + H_; k0 += 16) {
        #pragma unroll
        for (int e = tid; e < 64 * 16; e += 256) {
            int bb = e >> 4, kk = e & 15;
            int k = k0 + kk;
            xs[bb][kk] = (k < P_) ? g_ctx[bb * P_ + k] : h1old[bb * H_ + (k - P_)];
        }
        {
            int kk = tid >> 4, q = tid & 15;
            int k = k0 + kk;
            int col = (q >> 2) * H_ + j * 4 + (q & 3);
            ws[kk][q] = (k < P_) ? Wih1[(E_ + k) * (4 * H_) + col]
                                 : Whh1[(k - P_) * (4 * H_) + col];
        }
        __syncthreads();
        #pragma unroll
        for (int kk = 0; kk < 16; kk++) {
            float a0 = xs[ty * 2][kk], a1 = xs[ty * 2 + 1][kk];
            float w0 = ws[kk][tx * 2], w1 = ws[kk][tx * 2 + 1];
            acc[0][0] += a0 * w0; acc[0][1] += a0 * w1;
            acc[1][0] += a1 * w0; acc[1][1] += a1 * w1;
        }
        __syncthreads();
    }
    #pragma unroll
    for (int i = 0; i < 2; i++)
        #pragma unroll
        for (int jj = 0; jj < 2; jj++)
            gsm[ty * 2 + i][tx * 2 + jj] = acc[i][jj];
    __syncthreads();
    int b = tid >> 2, u = tid & 3;
    float iv = gsm[b][0 + u], fv = gsm[b][4 + u], gv = gsm[b][8 + u], ov = gsm[b][12 + u];
    int idx = b * H_ + j * 4 + u;
    float c = g_c1[idx];
    float cn = sigf(fv) * c + sigf(iv) * tanhf(gv);
    g_c1[idx] = cn;
    g_h1[pp ^ 1][idx] = sigf(ov) * tanhf(cn);
}

// ---------------- K2: LSTM2 --------------------------------------------------
// gates[b][col] = h1new[b]@W_ih2 + h2old[b]@W_hh2 + b_ih2 + b_hh2, 64 blocks.
__global__ void lstm2_kernel(const float* __restrict__ Wih2, const float* __restrict__ bih2,
                             const float* __restrict__ Whh2, const float* __restrict__ bhh2,
                             int pp) {
    __shared__ float xs[64][17];
    __shared__ float ws[16][17];
    __shared__ float gsm[64][17];
    int j = blockIdx.x;
    int tid = threadIdx.x;
    int tx = tid & 7, ty = tid >> 3;
    float acc[2][2];
    {
        #pragma unroll
        for (int jj = 0; jj < 2; jj++) {
            int q = tx * 2 + jj;
            int col = (q >> 2) * D_ + j * 4 + (q & 3);
            float bias = bih2[col] + bhh2[col];
            acc[0][jj] = bias; acc[1][jj] = bias;
        }
    }
    const float* __restrict__ h1new = g_h1[pp ^ 1];
    const float* __restrict__ h2old = g_h2[pp];
    for (int k0 = 0; k0 < H_ + D_; k0 += 16) {
        #pragma unroll
        for (int e = tid; e < 64 * 16; e += 256) {
            int bb = e >> 4, kk = e & 15;
            int k = k0 + kk;
            xs[bb][kk] = (k < H_) ? h1new[bb * H_ + k] : h2old[bb * D_ + (k - H_)];
        }
        {
            int kk = tid >> 4, q = tid & 15;
            int k = k0 + kk;
            int col = (q >> 2) * D_ + j * 4 + (q & 3);
            ws[kk][q] = (k < H_) ? Wih2[k * (4 * D_) + col]
                                 : Whh2[(k - H_) * (4 * D_) + col];
        }
        __syncthreads();
        #pragma unroll
        for (int kk = 0; kk < 16; kk++) {
            float a0 = xs[ty * 2][kk], a1 = xs[ty * 2 + 1][kk];
            float w0 = ws[kk][tx * 2], w1 = ws[kk][tx * 2 + 1];
            acc[0][0] += a0 * w0; acc[0][1] += a0 * w1;
            acc[1][0] += a1 * w0; acc[1][1] += a1 * w1;
        }
        __syncthreads();
    }
    #pragma unroll
    for (int i = 0; i < 2; i++)
        #pragma unroll
        for (int jj = 0; jj < 2; jj++)
            gsm[ty * 2 + i][tx * 2 + jj] = acc[i][jj];
    __syncthreads();
    int b = tid >> 2, u = tid & 3;
    float iv = gsm[b][0 + u], fv = gsm[b][4 + u], gv = gsm[b][8 + u], ov = gsm[b][12 + u];
    int idx = b * D_ + j * 4 + u;
    float c = g_c2[idx];
    float cn = sigf(fv) * c + sigf(iv) * tanhf(gv);
    g_c2[idx] = cn;
    g_h2[pp ^ 1][idx] = sigf(ov) * tanhf(cn);
}

// ---------------- K3: attention + logits (block per batch) ------------------
__global__ void attn_kernel(const float* __restrict__ Wq, const float* __restrict__ bq,
                            const float* __restrict__ embW, const float* __restrict__ char_b,
                            const int* __restrict__ lens,
                            float* __restrict__ pred, float* __restrict__ plot,
                            int t, int pp) {
    __shared__ float h2s[D_];
    __shared__ float qs[P_];
    __shared__ float ctxs[P_];
    __shared__ float sc[S_];
    __shared__ float red[256];
    int b = blockIdx.x;
    int tid = threadIdx.x;
    const float* __restrict__ h2new = g_h2[pp ^ 1];
    h2s[tid] = h2new[b * D_ + tid];
    __syncthreads();
    // q = h2 @ Wq + bq
    {
        float acc = bq[tid];
        #pragma unroll 4
        for (int h = 0; h < D_; h++) acc += h2s[h] * Wq[h * P_ + tid];
        qs[tid] = acc;
    }
    __syncthreads();
    int len = lens[b];
    const float scale = 0.0625f;            // 1/sqrt(256)
    int w = tid >> 5, lane = tid & 31;
    const float* __restrict__ kb = g_key + (size_t)b * S_ * P_;
    for (int it = 0; it < 25; it++) {
        int s0 = it * 32 + w * 4;
        const float* kp = kb + s0 * P_;
        float a0 = 0.f, a1 = 0.f, a2 = 0.f, a3 = 0.f;
        #pragma unroll
        for (int k8 = 0; k8 < 8; k8++) {
            int k = lane + k8 * 32;
            float qk = qs[k];
            a0 += kp[0 * P_ + k] * qk;
            a1 += kp[1 * P_ + k] * qk;
            a2 += kp[2 * P_ + k] * qk;
            a3 += kp[3 * P_ + k] * qk;
        }
        #pragma unroll
        for (int off = 16; off; off >>= 1) {
            a0 += __shfl_xor_sync(0xffffffffu, a0, off);
            a1 += __shfl_xor_sync(0xffffffffu, a1, off);
            a2 += __shfl_xor_sync(0xffffffffu, a2, off);
            a3 += __shfl_xor_sync(0xffffffffu, a3, off);
        }
        if (lane < 4) {
            float v = (lane == 0) ? a0 : (lane == 1) ? a1 : (lane == 2) ? a2 : a3;
            int s = s0 + lane;
            sc[s] = (s < len) ? v * scale : -1e9f;
        }
    }
    __syncthreads();
    // softmax over sc[0..799]
    float mx = -3.4e38f;
    for (int s = tid; s < S_; s += 256) mx = fmaxf(mx, sc[s]);
    red[tid] = mx; __syncthreads();
    for (int off = 128; off; off >>= 1) { if (tid < off) red[tid] = fmaxf(red[tid], red[tid + off]); __syncthreads(); }
    float M = red[0];
    __syncthreads();
    float sm = 0.f;
    for (int s = tid; s < S_; s += 256) { float e = __expf(sc[s] - M); sc[s] = e; sm += e; }
    red[tid] = sm; __syncthreads();
    for (int off = 128; off; off >>= 1) { if (tid < off) red[tid] += red[tid + off]; __syncthreads(); }
    float inv = 1.f / red[0];
    __syncthreads();
    // context = aw @ val_proj
    {
        const float* __restrict__ vp = g_val + (size_t)b * S_ * P_ + tid;
        float acc = 0.f;
        #pragma unroll 4
        for (int s = 0; s < S_; s++) acc += sc[s] * vp[(size_t)s * P_];
        float c = acc * inv;
        g_ctx[b * P_ + tid] = c;
        ctxs[tid] = c;
    }
    __syncthreads();
    // logits = [h2, context] @ embed_W.T + char_b
    for (int v = w; v < V_; v += 8) {
        float acc = 0.f;
        for (int e = lane; e < E_; e += 32) {
            float oe = (e < D_) ? h2s[e] : ctxs[e - D_];
            acc += oe * embW[v * E_ + e];
        }
        #pragma unroll
        for (int off = 16; off; off >>= 1) acc += __shfl_xor_sync(0xffffffffu, acc, off);
        if (lane == 0) pred[(b * T_ + t) * V_ + v] = acc + char_b[v];
    }
    // attention plot: aw[batch 0], column t of (S,T)
    if (b == 0) {
        for (int s = tid; s < S_; s += 256) plot[s * T_ + t] = sc[s] * inv;
    }
}

// ---------------- launch -----------------------------------------------------
extern "C" void kernel_launch(void* const* d_in, const int* in_sizes, int n_in,
                              void* d_out, int out_size) {
    const float* enc    = (const float*)d_in[0];
    const float* embW   = (const float*)d_in[1];
    const float* Wih1   = (const float*)d_in[2];
    const float* bih1   = (const float*)d_in[3];
    const float* Whh1   = (const float*)d_in[4];
    const float* bhh1   = (const float*)d_in[5];
    const float* Wih2   = (const float*)d_in[6];
    const float* bih2   = (const float*)d_in[7];
    const float* Whh2   = (const float*)d_in[8];
    const float* bhh2   = (const float*)d_in[9];
    const float* Wk     = (const float*)d_in[10];
    const float* bk     = (const float*)d_in[11];
    const float* Wv     = (const float*)d_in[12];
    const float* bv     = (const float*)d_in[13];
    const float* Wq     = (const float*)d_in[14];
    const float* bq     = (const float*)d_in[15];
    const float* char_b = (const float*)d_in[16];
    const int*   lens   = (const int*)d_in[17];
    const int*   y      = (const int*)d_in[18];

    float* pred = (float*)d_out;                 // (B, T, V)
    float* plot = pred + (size_t)B_ * T_ * V_;   // (S, T)

    dim3 kvgrid((2 * P_) / 32, (B_ * S_) / 32);  // (16, 1600)
    kv_proj_kernel<<<kvgrid, 256>>>(enc, Wk, bk, Wv, bv);
    embg_kernel<<<dim3((4 * H_) / 256, V_), 256>>>(embW, Wih1, bih1, bhh1);
    init_kernel<<<(B_ * H_) / 256, 256>>>();

    for (int t = 0; t < T_; t++) {
        int pp = t & 1;
        lstm1_kernel<<<128, 256>>>(Wih1, Whh1, y, t, pp);
        lstm2_kernel<<<64, 256>>>(Wih2, bih2, Whh2, bhh2, pp);
        attn_kernel<<<64, 256>>>(Wq, bq, embW, char_b, lens, pred, plot, t, pp);
    }
}

// round 4
// speedup vs baseline: 4.5990x; 4.5990x over previous
#include <cuda_runtime.h>
#include <math.h>

#define B_   64
#define S_   800
#define ENC_ 512
#define T_   250
#define V_   30
#define E_   512
#define H_   512
#define D_   256
#define P_   256
#define NBLK 128

// ---------------- device scratch ----------------
__device__ float g_val [B_*S_*P_];       // val_proj (B,S,P)
__device__ float g_keyq[B_*S_*D_];       // K'' = scale * key_proj @ Wq^T  (B,S,D)
__device__ float g_kbq [B_*S_];          // scale * key_proj . bq
__device__ float g_embg[V_*4*H_];        // embW@Wih1[0:512] + bih1 + bhh1
__device__ float g_wfold[ENC_*D_];       // scale * Wk @ Wq^T   (512,256)
__device__ float g_bfold[D_];            // scale * bk @ Wq^T
__device__ float g_wb[ENC_];             // scale * Wk @ bq
__device__ float g_c0[1];                // scale * bk . bq
__device__ float g_h1[B_*H_];
__device__ float g_c1[B_*H_];
__device__ float g_h2[B_*D_];
__device__ float g_c2[B_*D_];
__device__ float g_ctx[B_*P_];
__device__ float g_gp1[4*B_*4*H_];       // lstm1 gate partials (4 K-slices)
__device__ float g_gp2[8*B_*4*D_];       // lstm2 gate partials (8 K-slices)

// ---------------- grid barrier state ----------------
__device__ unsigned g_bar_count;
__device__ unsigned g_bar_gen;

__device__ __forceinline__ void gbar() {
    __syncthreads();
    if (threadIdx.x == 0) {
        unsigned gen = *(volatile unsigned*)&g_bar_gen;
        __threadfence();
        if (atomicAdd(&g_bar_count, 1u) == NBLK - 1u) {
            g_bar_count = 0u;
            __threadfence();
            *(volatile unsigned*)&g_bar_gen = gen + 1u;
        } else {
            while (*(volatile unsigned*)&g_bar_gen == gen) __nanosleep(32);
            __threadfence();
        }
    }
    __syncthreads();
}

__device__ __forceinline__ float sigf(float x) { return 1.0f / (1.0f + expf(-x)); }
__device__ __forceinline__ float dot4(float4 a, float4 b) {
    return a.x*b.x + a.y*b.y + a.z*b.z + a.w*b.w;
}

#define GEMM_FMA16()                                             \
    do {                                                          \
        acc00 += a.x*wv.x; acc01 += a.x*wv.y; acc02 += a.x*wv.z; acc03 += a.x*wv.w; \
        acc10 += a.y*wv.x; acc11 += a.y*wv.y; acc12 += a.y*wv.z; acc13 += a.y*wv.w; \
        acc20 += a.z*wv.x; acc21 += a.z*wv.y; acc22 += a.z*wv.z; acc23 += a.z*wv.w; \
        acc30 += a.w*wv.x; acc31 += a.w*wv.y; acc32 += a.w*wv.z; acc33 += a.w*wv.w; \
    } while (0)

#define GEMM_DECL_ACC()                                          \
    float acc00=0,acc01=0,acc02=0,acc03=0, acc10=0,acc11=0,acc12=0,acc13=0, \
          acc20=0,acc21=0,acc22=0,acc23=0, acc30=0,acc31=0,acc32=0,acc33=0

// ================== precompute kernels (unchanged from R3) ==================
__global__ void wfold_kernel(const float* __restrict__ Wk, const float* __restrict__ Wq) {
    __shared__ float xs[32][68];
    __shared__ float ws[32][68];
    int n0 = blockIdx.x * 64;
    int m0 = blockIdx.y * 64;
    int tid = threadIdx.x;
    int cg = tid & 15, bg = tid >> 4;
    GEMM_DECL_ACC();
    for (int k0 = 0; k0 < P_; k0 += 32) {
        #pragma unroll
        for (int e = tid; e < 2048; e += 256) {
            int kk = e & 31, m = e >> 5;
            xs[kk][m] = Wk[(m0 + m) * P_ + k0 + kk];
        }
        #pragma unroll
        for (int e = tid; e < 2048; e += 256) {
            int kk = e & 31, h = e >> 5;
            ws[kk][h] = Wq[(n0 + h) * P_ + k0 + kk];
        }
        __syncthreads();
        #pragma unroll
        for (int kk = 0; kk < 32; kk++) {
            float4 a  = *(const float4*)&xs[kk][bg * 4];
            float4 wv = *(const float4*)&ws[kk][cg * 4];
            GEMM_FMA16();
        }
        __syncthreads();
    }
    const float sc = 0.0625f;
    float accs[4][4] = {{acc00,acc01,acc02,acc03},{acc10,acc11,acc12,acc13},
                        {acc20,acc21,acc22,acc23},{acc30,acc31,acc32,acc33}};
    #pragma unroll
    for (int i = 0; i < 4; i++) {
        float4 r = make_float4(accs[i][0]*sc, accs[i][1]*sc, accs[i][2]*sc, accs[i][3]*sc);
        *(float4*)&g_wfold[(size_t)(m0 + bg*4 + i) * D_ + n0 + cg*4] = r;
    }
}

__global__ void vec_kernel(const float* __restrict__ Wk, const float* __restrict__ Wq,
                           const float* __restrict__ bk, const float* __restrict__ bq) {
    int tid = threadIdx.x;   // 512 threads
    const float sc = 0.0625f;
    if (tid < D_) {
        float a = 0.f;
        for (int p = 0; p < P_; p++) a += bk[p] * Wq[tid * P_ + p];
        g_bfold[tid] = a * sc;
    }
    {
        float a = 0.f;
        for (int p = 0; p < P_; p++) a += Wk[tid * P_ + p] * bq[p];
        g_wb[tid] = a * sc;
    }
    if (tid == 0) {
        float a = 0.f;
        for (int p = 0; p < P_; p++) a += bk[p] * bq[p];
        g_c0[0] = a * sc;
        g_bar_count = 0u;        // barrier state (idempotent; always 0 post-run)
    }
}

__global__ void main_gemm(const float* __restrict__ enc,
                          const float* __restrict__ Wv, const float* __restrict__ bv) {
    __shared__ float xs[32][68];
    __shared__ float ws[32][68];
    int n0 = blockIdx.x * 64;
    int m0 = blockIdx.y * 64;
    int tid = threadIdx.x;
    int cg = tid & 15, bg = tid >> 4;
    bool isval = (n0 < P_);
    const float* __restrict__ Bsrc = isval ? (Wv + n0) : (g_wfold + (n0 - P_));
    GEMM_DECL_ACC();
    for (int k0 = 0; k0 < ENC_; k0 += 32) {
        #pragma unroll
        for (int e = tid; e < 2048; e += 256) {
            int kk = e & 31, m = e >> 5;
            xs[kk][m] = enc[(size_t)(m0 + m) * ENC_ + k0 + kk];
        }
        #pragma unroll
        for (int e = tid; e < 2048; e += 256) {
            int c = e & 63, kk = e >> 6;
            ws[kk][c] = Bsrc[(size_t)(k0 + kk) * P_ + c];
        }
        __syncthreads();
        #pragma unroll
        for (int kk = 0; kk < 32; kk++) {
            float4 a  = *(const float4*)&xs[kk][bg * 4];
            float4 wv = *(const float4*)&ws[kk][cg * 4];
            GEMM_FMA16();
        }
        __syncthreads();
    }
    float4 bias = isval ? *(const float4*)&bv[n0 + cg*4]
                        : *(const float4*)&g_bfold[n0 - P_ + cg*4];
    float* __restrict__ outp = isval ? g_val : g_keyq;
    int colbase = isval ? n0 : (n0 - P_);
    float accs[4][4] = {{acc00,acc01,acc02,acc03},{acc10,acc11,acc12,acc13},
                        {acc20,acc21,acc22,acc23},{acc30,acc31,acc32,acc33}};
    #pragma unroll
    for (int i = 0; i < 4; i++) {
        float4 r = make_float4(accs[i][0]+bias.x, accs[i][1]+bias.y,
                               accs[i][2]+bias.z, accs[i][3]+bias.w);
        *(float4*)&outp[(size_t)(m0 + bg*4 + i) * P_ + colbase + cg*4] = r;
    }
}

__global__ void kbq_kernel(const float* __restrict__ enc) {
    __shared__ float wbs[ENC_];
    int tid = threadIdx.x, w = tid >> 5, lane = tid & 31;
    wbs[tid] = g_wb[tid]; wbs[256 + tid] = g_wb[256 + tid];
    __syncthreads();
    float4 w0 = *(const float4*)&wbs[lane*4];
    float4 w1 = *(const float4*)&wbs[128 + lane*4];
    float4 w2 = *(const float4*)&wbs[256 + lane*4];
    float4 w3 = *(const float4*)&wbs[384 + lane*4];
    float c0 = g_c0[0];
    int row0 = blockIdx.x * 256 + w * 32;
    for (int r = 0; r < 32; r++) {
        int row = row0 + r;
        const float4* ep = (const float4*)(enc + (size_t)row * ENC_);
        float acc = dot4(ep[lane], w0) + dot4(ep[32+lane], w1)
                  + dot4(ep[64+lane], w2) + dot4(ep[96+lane], w3);
        #pragma unroll
        for (int off = 16; off; off >>= 1) acc += __shfl_xor_sync(0xffffffffu, acc, off);
        if (lane == 0) g_kbq[row] = acc + c0;
    }
}

__global__ void embg_kernel(const float* __restrict__ embW, const float* __restrict__ Wih1,
                            const float* __restrict__ bih1, const float* __restrict__ bhh1) {
    __shared__ float es[E_];
    int v = blockIdx.y;
    int g = blockIdx.x * 256 + threadIdx.x;
    for (int e = threadIdx.x; e < E_; e += 256) es[e] = embW[v * E_ + e];
    __syncthreads();
    float acc = bih1[g] + bhh1[g];
    #pragma unroll 4
    for (int e = 0; e < E_; e++) acc += es[e] * Wih1[e * (4 * H_) + g];
    g_embg[v * (4 * H_) + g] = acc;
}

__global__ void init_kernel(const float* __restrict__ enc,
                            const float* __restrict__ Wk, const float* __restrict__ bk) {
    __shared__ float es[ENC_];
    int b = blockIdx.x, u = threadIdx.x;
    es[u] = enc[(size_t)b * S_ * ENC_ + u];
    es[u + 256] = enc[(size_t)b * S_ * ENC_ + 256 + u];
    __syncthreads();
    g_h1[b*H_ + u] = 0.f;       g_h1[b*H_ + 256 + u] = 0.f;
    g_c1[b*H_ + u] = 0.f;       g_c1[b*H_ + 256 + u] = 0.f;
    g_h2[b*D_ + u] = 0.f;       g_c2[b*D_ + u] = 0.f;
    float acc = bk[u];
    #pragma unroll 4
    for (int k = 0; k < ENC_; k++) acc += es[k] * Wk[k * P_ + u];
    g_ctx[b*P_ + u] = acc;
}

// ================== persistent decode kernel ==================
__global__ void __launch_bounds__(256, 1)
persist_kernel(const float* __restrict__ Wih1, const float* __restrict__ Whh1,
               const float* __restrict__ Wih2, const float* __restrict__ bih2,
               const float* __restrict__ Whh2, const float* __restrict__ bhh2,
               const float* __restrict__ embW, const float* __restrict__ char_b,
               const int* __restrict__ lens, const int* __restrict__ y,
               float* __restrict__ pred, float* __restrict__ plot)
{
    __shared__ __align__(16) float sh[4352];
    int tid = threadIdx.x;
    int bid = blockIdx.x;
    int cg = tid & 15, bg = tid >> 4;
    int w = tid >> 5, lane = tid & 31;

    for (int t = 0; t < T_; t++) {
        // ---------- P1: LSTM1 gemm partials (32 col-tiles x 4 K-slices) ----------
        {
            float* xs = sh;            // [32][68]
            float* ws = sh + 2176;     // [32][68]
            int ct = bid >> 2, ks = bid & 3;
            int c0col = ct * 64;
            int kbase = ks * 192;
            GEMM_DECL_ACC();
            for (int k0 = kbase; k0 < kbase + 192; k0 += 32) {
                bool inctx = (k0 < P_);
                #pragma unroll
                for (int e = tid; e < 2048; e += 256) {
                    int kk = e & 31, m = e >> 5;
                    int k = k0 + kk;
                    xs[kk*68 + m] = inctx ? g_ctx[m * P_ + k] : g_h1[m * H_ + (k - P_)];
                }
                #pragma unroll
                for (int e = tid; e < 2048; e += 256) {
                    int c = e & 63, kk = e >> 6;
                    int k = k0 + kk;
                    ws[kk*68 + c] = inctx ? Wih1[(size_t)(E_ + k) * (4*H_) + c0col + c]
                                          : Whh1[(size_t)(k - P_) * (4*H_) + c0col + c];
                }
                __syncthreads();
                #pragma unroll
                for (int kk = 0; kk < 32; kk++) {
                    float4 a  = *(const float4*)&xs[kk*68 + bg * 4];
                    float4 wv = *(const float4*)&ws[kk*68 + cg * 4];
                    GEMM_FMA16();
                }
                __syncthreads();
            }
            float accs[4][4] = {{acc00,acc01,acc02,acc03},{acc10,acc11,acc12,acc13},
                                {acc20,acc21,acc22,acc23},{acc30,acc31,acc32,acc33}};
            float* outp = g_gp1 + (size_t)ks * (B_ * 4*H_);
            #pragma unroll
            for (int i = 0; i < 4; i++) {
                float4 r = make_float4(accs[i][0], accs[i][1], accs[i][2], accs[i][3]);
                *(float4*)&outp[(size_t)(bg*4 + i) * (4*H_) + c0col + cg*4] = r;
            }
        }
        gbar();

        // ---------- P2: cell1 ----------
        {
            int idx = bid * 256 + tid;          // 32768 = B*H
            int b = idx >> 9, u = idx & 511;
            int tok = (t == 0) ? 0 : y[b * T_ + (t - 1)];
            float G[4];
            #pragma unroll
            for (int g = 0; g < 4; g++) {
                int col = g * H_ + u;
                float s = g_embg[tok * (4*H_) + col];
                #pragma unroll
                for (int ks = 0; ks < 4; ks++)
                    s += g_gp1[(size_t)ks * (B_*4*H_) + b * (4*H_) + col];
                G[g] = s;
            }
            float c = g_c1[idx];
            float cn = sigf(G[1]) * c + sigf(G[0]) * tanhf(G[2]);
            g_c1[idx] = cn;
            g_h1[idx] = sigf(G[3]) * tanhf(cn);
        }
        gbar();

        // ---------- P3: LSTM2 gemm partials (16 col-tiles x 8 K-slices of 96) ----------
        {
            float* xs = sh;
            float* ws = sh + 2176;
            int ct = bid >> 3, ks = bid & 7;
            int c0col = ct * 64;
            int kbase = ks * 96;
            GEMM_DECL_ACC();
            for (int k0 = kbase; k0 < kbase + 96; k0 += 32) {
                bool inh1 = (k0 < H_);
                #pragma unroll
                for (int e = tid; e < 2048; e += 256) {
                    int kk = e & 31, m = e >> 5;
                    int k = k0 + kk;
                    xs[kk*68 + m] = inh1 ? g_h1[m * H_ + k] : g_h2[m * D_ + (k - H_)];
                }
                #pragma unroll
                for (int e = tid; e < 2048; e += 256) {
                    int c = e & 63, kk = e >> 6;
                    int k = k0 + kk;
                    ws[kk*68 + c] = inh1 ? Wih2[(size_t)k * (4*D_) + c0col + c]
                                         : Whh2[(size_t)(k - H_) * (4*D_) + c0col + c];
                }
                __syncthreads();
                #pragma unroll
                for (int kk = 0; kk < 32; kk++) {
                    float4 a  = *(const float4*)&xs[kk*68 + bg * 4];
                    float4 wv = *(const float4*)&ws[kk*68 + cg * 4];
                    GEMM_FMA16();
                }
                __syncthreads();
            }
            float accs[4][4] = {{acc00,acc01,acc02,acc03},{acc10,acc11,acc12,acc13},
                                {acc20,acc21,acc22,acc23},{acc30,acc31,acc32,acc33}};
            float* outp = g_gp2 + (size_t)ks * (B_ * 4*D_);
            #pragma unroll
            for (int i = 0; i < 4; i++) {
                float4 r = make_float4(accs[i][0], accs[i][1], accs[i][2], accs[i][3]);
                *(float4*)&outp[(size_t)(bg*4 + i) * (4*D_) + c0col + cg*4] = r;
            }
        }
        gbar();

        // ---------- P4: cell2 + attention + logits (block per batch) ----------
        if (bid < B_) {
            float* h2s  = sh;                      // 256
            float* ctxs = sh + 256;                // 256
            float* sc   = sh + 512;                // 800
            float* red  = sh + 1312;               // 256
            float4* red4 = (float4*)(sh + 1568);   // 256 float4
            int b = bid;

            // cell2
            {
                int u = tid;
                float G[4];
                #pragma unroll
                for (int g = 0; g < 4; g++) {
                    int col = g * D_ + u;
                    float s = bih2[col] + bhh2[col];
                    #pragma unroll
                    for (int ks = 0; ks < 8; ks++)
                        s += g_gp2[(size_t)ks * (B_*4*D_) + b * (4*D_) + col];
                    G[g] = s;
                }
                int idx = b * D_ + u;
                float c = g_c2[idx];
                float cn = sigf(G[1]) * c + sigf(G[0]) * tanhf(G[2]);
                g_c2[idx] = cn;
                float hn = sigf(G[3]) * tanhf(cn);
                g_h2[idx] = hn;
                h2s[u] = hn;
            }
            __syncthreads();
            int len = lens[b];

            // scores
            {
                float4 q0 = *(const float4*)&h2s[lane*4];
                float4 q1 = *(const float4*)&h2s[128 + lane*4];
                const float* __restrict__ kb = g_keyq + (size_t)b * S_ * D_;
                const float* __restrict__ kq = g_kbq + b * S_;
                for (int j = 0; j < 25; j++) {
                    int sb = w + 32 * j;
                    float a0 = 0.f, a1 = 0.f, a2 = 0.f, a3 = 0.f;
                    if (sb < len) {
                        const float4* p = (const float4*)(kb + (size_t)sb * D_);
                        a0 = dot4(q0, p[lane]) + dot4(q1, p[32 + lane]);
                    }
                    if (sb + 8 < len) {
                        const float4* p = (const float4*)(kb + (size_t)(sb+8) * D_);
                        a1 = dot4(q0, p[lane]) + dot4(q1, p[32 + lane]);
                    }
                    if (sb + 16 < len) {
                        const float4* p = (const float4*)(kb + (size_t)(sb+16) * D_);
                        a2 = dot4(q0, p[lane]) + dot4(q1, p[32 + lane]);
                    }
                    if (sb + 24 < len) {
                        const float4* p = (const float4*)(kb + (size_t)(sb+24) * D_);
                        a3 = dot4(q0, p[lane]) + dot4(q1, p[32 + lane]);
                    }
                    #pragma unroll
                    for (int off = 16; off; off >>= 1) {
                        a0 += __shfl_xor_sync(0xffffffffu, a0, off);
                        a1 += __shfl_xor_sync(0xffffffffu, a1, off);
                        a2 += __shfl_xor_sync(0xffffffffu, a2, off);
                        a3 += __shfl_xor_sync(0xffffffffu, a3, off);
                    }
                    if (lane < 4) {
                        int s = sb + 8 * lane;
                        float v = (lane == 0) ? a0 : (lane == 1) ? a1 : (lane == 2) ? a2 : a3;
                        sc[s] = (s < len) ? v + kq[s] : -1e9f;
                    }
                }
            }
            __syncthreads();

            // softmax
            float mx = -3.4e38f;
            for (int s = tid; s < S_; s += 256) mx = fmaxf(mx, sc[s]);
            red[tid] = mx; __syncthreads();
            for (int off = 128; off; off >>= 1) { if (tid < off) red[tid] = fmaxf(red[tid], red[tid+off]); __syncthreads(); }
            float M = red[0];
            __syncthreads();
            float sm = 0.f;
            for (int s = tid; s < S_; s += 256) { float e = __expf(sc[s] - M); sc[s] = e; sm += e; }
            red[tid] = sm; __syncthreads();
            for (int off = 128; off; off >>= 1) { if (tid < off) red[tid] += red[tid+off]; __syncthreads(); }
            float inv = 1.f / red[0];
            __syncthreads();

            // context
            {
                int sl = tid >> 6, p4 = tid & 63;
                const float4* __restrict__ vp = (const float4*)(g_val + (size_t)b * S_ * P_) + p4;
                float4 acc = make_float4(0.f, 0.f, 0.f, 0.f);
                int send = sl * 200 + 200; if (send > len) send = len;
                for (int s = sl * 200; s < send; s++) {
                    float wgt = sc[s];
                    float4 v = vp[(size_t)s * 64];
                    acc.x += wgt * v.x; acc.y += wgt * v.y; acc.z += wgt * v.z; acc.w += wgt * v.w;
                }
                red4[tid] = acc;
            }
            __syncthreads();
            if (tid < 64) {
                float4 a = red4[tid], b1 = red4[64+tid], c1 = red4[128+tid], d1 = red4[192+tid];
                float4 r = make_float4((a.x+b1.x+c1.x+d1.x)*inv, (a.y+b1.y+c1.y+d1.y)*inv,
                                       (a.z+b1.z+c1.z+d1.z)*inv, (a.w+b1.w+c1.w+d1.w)*inv);
                *(float4*)&ctxs[tid*4] = r;
                *(float4*)&g_ctx[b*P_ + tid*4] = r;
            }
            __syncthreads();

            // logits
            {
                float4 o0 = *(const float4*)&h2s[lane*4];
                float4 o1 = *(const float4*)&h2s[128 + lane*4];
                float4 o2 = *(const float4*)&ctxs[lane*4];
                float4 o3 = *(const float4*)&ctxs[128 + lane*4];
                for (int v = w; v < V_; v += 8) {
                    const float4* ev = (const float4*)(embW + (size_t)v * E_);
                    float acc = dot4(o0, ev[lane]) + dot4(o1, ev[32+lane])
                              + dot4(o2, ev[64+lane]) + dot4(o3, ev[96+lane]);
                    #pragma unroll
                    for (int off = 16; off; off >>= 1) acc += __shfl_xor_sync(0xffffffffu, acc, off);
                    if (lane == 0) pred[((size_t)b * T_ + t) * V_ + v] = acc + char_b[v];
                }
            }
            if (b == 0) {
                for (int s = tid; s < S_; s += 256) plot[s * T_ + t] = sc[s] * inv;
            }
        }
        gbar();
    }
}

// ---------------- launch -----------------------------------------------------
extern "C" void kernel_launch(void* const* d_in, const int* in_sizes, int n_in,
                              void* d_out, int out_size) {
    const float* enc    = (const float*)d_in[0];
    const float* embW   = (const float*)d_in[1];
    const float* Wih1   = (const float*)d_in[2];
    const float* bih1   = (const float*)d_in[3];
    const float* Whh1   = (const float*)d_in[4];
    const float* bhh1   = (const float*)d_in[5];
    const float* Wih2   = (const float*)d_in[6];
    const float* bih2   = (const float*)d_in[7];
    const float* Whh2   = (const float*)d_in[8];
    const float* bhh2   = (const float*)d_in[9];
    const float* Wk     = (const float*)d_in[10];
    const float* bk     = (const float*)d_in[11];
    const float* Wv     = (const float*)d_in[12];
    const float* bv     = (const float*)d_in[13];
    const float* Wq     = (const float*)d_in[14];
    const float* bq     = (const float*)d_in[15];
    const float* char_b = (const float*)d_in[16];
    const int*   lens   = (const int*)d_in[17];
    const int*   y      = (const int*)d_in[18];

    float* pred = (float*)d_out;                 // (B, T, V)
    float* plot = pred + (size_t)B_ * T_ * V_;   // (S, T)

    // precompute (6 nodes)
    wfold_kernel<<<dim3(4, 8), 256>>>(Wk, Wq);
    vec_kernel<<<1, 512>>>(Wk, Wq, bk, bq);
    main_gemm<<<dim3(8, (B_*S_)/64), 256>>>(enc, Wv, bv);
    kbq_kernel<<<(B_*S_)/256, 256>>>(enc);
    embg_kernel<<<dim3(8, V_), 256>>>(embW, Wih1, bih1, bhh1);
    init_kernel<<<B_, 256>>>(enc, Wk, bk);

    // whole decode loop: 1 node
    persist_kernel<<<NBLK, 256>>>(Wih1, Whh1, Wih2, bih2, Whh2, bhh2,
                                  embW, char_b, lens, y, pred, plot);
}

// round 5
// speedup vs baseline: 6.7809x; 1.4744x over previous
#include <cuda_runtime.h>
#include <math.h>

#define B_   64
#define S_   800
#define ENC_ 512
#define T_   250
#define V_   30
#define E_   512
#define H_   512
#define D_   256
#define P_   256
#define NBLK 128
#define G1   (4*H_)
#define G2   (4*D_)

// ---------------- device scratch ----------------
__device__ float g_val [B_*S_*P_];       // val_proj (B,S,P)
__device__ float g_keyq[B_*S_*D_];       // K'' = scale * key_proj @ Wq^T  (B,S,D)
__device__ float g_kbq [B_*S_];          // scale * key_proj . bq
__device__ float g_embg[V_*G1];          // embW@Wih1[0:512] + bih1 + bhh1
__device__ float g_wfold[ENC_*D_];       // scale * Wk @ Wq^T
__device__ float g_bfold[D_];
__device__ float g_wb[ENC_];
__device__ float g_c0[1];
__device__ float g_h1[B_*H_];
__device__ float g_c1[B_*H_];
__device__ float g_h2[2][B_*D_];
__device__ float g_c2[2][B_*D_];
__device__ float g_ctxp[2][B_*P_];       // context halves (sum = context)
__device__ float g_sc[B_*S_];            // raw masked scores
__device__ float g_gp1[4*B_*G1];         // lstm1 gate partials (4 K-slices)
__device__ float g_gp2[8*B_*G2];         // lstm2 gate partials (8 K-slices)

__device__ unsigned g_bar_count;         // zero-init; returns to 0 every barrier
__device__ unsigned g_bar_gen;

__device__ __forceinline__ void gbar() {
    __syncthreads();
    if (threadIdx.x == 0) {
        unsigned gen = *(volatile unsigned*)&g_bar_gen;
        __threadfence();
        if (atomicAdd(&g_bar_count, 1u) == NBLK - 1u) {
            g_bar_count = 0u;
            __threadfence();
            *(volatile unsigned*)&g_bar_gen = gen + 1u;
        } else {
            while (*(volatile unsigned*)&g_bar_gen == gen) __nanosleep(16);
            __threadfence();
        }
    }
    __syncthreads();
}

__device__ __forceinline__ float sigf(float x) { return 1.0f / (1.0f + expf(-x)); }
__device__ __forceinline__ float dot4(float4 a, float4 b) {
    return a.x*b.x + a.y*b.y + a.z*b.z + a.w*b.w;
}

#define GEMM_FMA16()                                             \
    do {                                                          \
        acc00 += a.x*wv.x; acc01 += a.x*wv.y; acc02 += a.x*wv.z; acc03 += a.x*wv.w; \
        acc10 += a.y*wv.x; acc11 += a.y*wv.y; acc12 += a.y*wv.z; acc13 += a.y*wv.w; \
        acc20 += a.z*wv.x; acc21 += a.z*wv.y; acc22 += a.z*wv.z; acc23 += a.z*wv.w; \
        acc30 += a.w*wv.x; acc31 += a.w*wv.y; acc32 += a.w*wv.z; acc33 += a.w*wv.w; \
    } while (0)

#define GEMM_DECL_ACC()                                          \
    float acc00=0,acc01=0,acc02=0,acc03=0, acc10=0,acc11=0,acc12=0,acc13=0, \
          acc20=0,acc21=0,acc22=0,acc23=0, acc30=0,acc31=0,acc32=0,acc33=0

// ================== the ONE kernel ==================
__global__ void __launch_bounds__(256, 1)
persist_kernel(const float* __restrict__ enc,  const float* __restrict__ embW,
               const float* __restrict__ Wih1, const float* __restrict__ bih1,
               const float* __restrict__ Whh1, const float* __restrict__ bhh1,
               const float* __restrict__ Wih2, const float* __restrict__ bih2,
               const float* __restrict__ Whh2, const float* __restrict__ bhh2,
               const float* __restrict__ Wk,   const float* __restrict__ bk,
               const float* __restrict__ Wv,   const float* __restrict__ bv,
               const float* __restrict__ Wq,   const float* __restrict__ bq,
               const float* __restrict__ char_b,
               const int* __restrict__ lens,   const int* __restrict__ y,
               float* __restrict__ pred,       float* __restrict__ plot)
{
    __shared__ __align__(16) float sh[4352];
    float* xs = sh;            // [32][68]
    float* ws = sh + 2176;     // [32][68]
    const int tid = threadIdx.x;
    const int bid = blockIdx.x;
    const int cg = tid & 15, bg = tid >> 4;
    const int w  = tid >> 5,  lane = tid & 31;
    const float scl = 0.0625f;  // 1/sqrt(256)

    // ============ PHASE A: weight folds, embg table, state init ============
    if (bid < 32) {
        // wfold tile: scale * Wk @ Wq^T
        int n0 = (bid & 3) * 64, m0 = (bid >> 2) * 64;
        GEMM_DECL_ACC();
        for (int k0 = 0; k0 < P_; k0 += 32) {
            #pragma unroll
            for (int e = tid; e < 2048; e += 256) {
                int kk = e & 31, m = e >> 5;
                xs[kk*68 + m] = Wk[(m0 + m) * P_ + k0 + kk];
            }
            #pragma unroll
            for (int e = tid; e < 2048; e += 256) {
                int kk = e & 31, h = e >> 5;
                ws[kk*68 + h] = Wq[(n0 + h) * P_ + k0 + kk];
            }
            __syncthreads();
            #pragma unroll
            for (int kk = 0; kk < 32; kk++) {
                float4 a  = *(const float4*)&xs[kk*68 + bg * 4];
                float4 wv = *(const float4*)&ws[kk*68 + cg * 4];
                GEMM_FMA16();
            }
            __syncthreads();
        }
        float accs[4][4] = {{acc00,acc01,acc02,acc03},{acc10,acc11,acc12,acc13},
                            {acc20,acc21,acc22,acc23},{acc30,acc31,acc32,acc33}};
        #pragma unroll
        for (int i = 0; i < 4; i++) {
            float4 r = make_float4(accs[i][0]*scl, accs[i][1]*scl, accs[i][2]*scl, accs[i][3]*scl);
            *(float4*)&g_wfold[(size_t)(m0 + bg*4 + i) * D_ + n0 + cg*4] = r;
        }
    } else if (bid < 34) {
        int e = (bid - 32) * 256 + tid;
        float a = 0.f;
        for (int p = 0; p < P_; p++) a += Wk[e * P_ + p] * bq[p];
        g_wb[e] = a * scl;
    } else if (bid == 34) {
        float a = 0.f;
        for (int p = 0; p < P_; p++) a += bk[p] * Wq[tid * P_ + p];
        g_bfold[tid] = a * scl;
        if (tid == 0) {
            float c = 0.f;
            for (int p = 0; p < P_; p++) c += bk[p] * bq[p];
            g_c0[0] = c * scl;
        }
    } else if (bid < 65) {
        // embg: v = bid-35
        int v = bid - 35;
        float* es = sh;
        for (int e = tid; e < E_; e += 256) es[e] = embW[v * E_ + e];
        __syncthreads();
        #pragma unroll
        for (int r = 0; r < 8; r++) {
            int g = tid + 256 * r;
            float acc = bih1[g] + bhh1[g];
            #pragma unroll 4
            for (int e = 0; e < E_; e++) acc += es[e] * Wih1[(size_t)e * G1 + g];
            g_embg[v * G1 + g] = acc;
        }
    } else if (bid >= 96) {
        int seg = bid - 96;                      // 0..31
        for (int j = tid; j < 1024; j += 256) {
            int i = seg * 1024 + j;
            g_h1[i] = 0.f; g_c1[i] = 0.f;
            if (i < B_*D_) { g_h2[0][i] = 0.f; g_h2[1][i] = 0.f;
                             g_c2[0][i] = 0.f; g_c2[1][i] = 0.f; }
        }
        // ctx init: ctxp[0][b] = enc[b,0,:]@Wk + bk ; ctxp[1][b] = 0
        float* es = sh;
        for (int bb = 0; bb < 2; bb++) {
            int b = seg * 2 + bb;
            __syncthreads();
            es[tid] = enc[(size_t)b * S_ * ENC_ + tid];
            es[tid + 256] = enc[(size_t)b * S_ * ENC_ + 256 + tid];
            __syncthreads();
            float acc = bk[tid];
            #pragma unroll 4
            for (int k = 0; k < ENC_; k++) acc += es[k] * Wk[k * P_ + tid];
            g_ctxp[0][b * P_ + tid] = acc;
            g_ctxp[1][b * P_ + tid] = 0.f;
        }
    }
    gbar();

    // ============ PHASE B: main precompute GEMM + kbq ============
    {
        // out(51200 x 512) = enc @ [Wv | Wfold]; 6400 tiles over 128 blocks
        for (int q = 0; q < 50; q++) {
            int tt = bid + NBLK * q;
            int n0 = (tt & 7) * 64, m0 = (tt >> 3) * 64;
            bool isval = (n0 < P_);
            const float* __restrict__ Bsrc = isval ? (Wv + n0) : (g_wfold + (n0 - P_));
            GEMM_DECL_ACC();
            for (int k0 = 0; k0 < ENC_; k0 += 32) {
                #pragma unroll
                for (int e = tid; e < 2048; e += 256) {
                    int kk = e & 31, m = e >> 5;
                    xs[kk*68 + m] = enc[(size_t)(m0 + m) * ENC_ + k0 + kk];
                }
                #pragma unroll
                for (int e = tid; e < 2048; e += 256) {
                    int c = e & 63, kk = e >> 6;
                    ws[kk*68 + c] = Bsrc[(size_t)(k0 + kk) * P_ + c];
                }
                __syncthreads();
                #pragma unroll
                for (int kk = 0; kk < 32; kk++) {
                    float4 a  = *(const float4*)&xs[kk*68 + bg * 4];
                    float4 wv = *(const float4*)&ws[kk*68 + cg * 4];
                    GEMM_FMA16();
                }
                __syncthreads();
            }
            float4 bias = isval ? *(const float4*)&bv[n0 + cg*4]
                                : *(const float4*)&g_bfold[n0 - P_ + cg*4];
            float* __restrict__ outp = isval ? g_val : g_keyq;
            int colbase = isval ? n0 : (n0 - P_);
            float accs[4][4] = {{acc00,acc01,acc02,acc03},{acc10,acc11,acc12,acc13},
                                {acc20,acc21,acc22,acc23},{acc30,acc31,acc32,acc33}};
            #pragma unroll
            for (int i = 0; i < 4; i++) {
                float4 r = make_float4(accs[i][0]+bias.x, accs[i][1]+bias.y,
                                       accs[i][2]+bias.z, accs[i][3]+bias.w);
                *(float4*)&outp[(size_t)(m0 + bg*4 + i) * P_ + colbase + cg*4] = r;
            }
        }
        // kbq: 400 rows per block
        __syncthreads();
        float* wbs = sh;
        wbs[tid] = g_wb[tid]; wbs[256 + tid] = g_wb[256 + tid];
        __syncthreads();
        float4 w0 = *(const float4*)&wbs[lane*4];
        float4 w1 = *(const float4*)&wbs[128 + lane*4];
        float4 w2 = *(const float4*)&wbs[256 + lane*4];
        float4 w3 = *(const float4*)&wbs[384 + lane*4];
        float c0 = g_c0[0];
        int r0 = bid * 400 + w * 50;
        for (int i = 0; i < 50; i++) {
            int row = r0 + i;
            const float4* ep = (const float4*)(enc + (size_t)row * ENC_);
            float acc = dot4(ep[lane], w0) + dot4(ep[32+lane], w1)
                      + dot4(ep[64+lane], w2) + dot4(ep[96+lane], w3);
            #pragma unroll
            for (int off = 16; off; off >>= 1) acc += __shfl_xor_sync(0xffffffffu, acc, off);
            if (lane == 0) g_kbq[row] = acc + c0;
        }
    }
    gbar();

    // ============ DECODE LOOP ============
    const int kkx = tid & 31, mx = tid >> 5;   // gemm x-load map
    const int cw  = tid & 63, kw = tid >> 6;   // gemm w-load map

    for (int t = 0; t < T_; t++) {
        const int pp = t & 1;

        // ---------- P1: LSTM1 gemm partials (32 col-tiles x 4 K-slices) ----------
        {
            int ct = bid >> 2, ks = bid & 3;
            int c0col = ct * 64;
            int kbase = ks * 192;
            float rx[8], rw[8];
            auto loadX = [&](int k0) {
                if (k0 < P_) {
                    #pragma unroll
                    for (int r = 0; r < 8; r++) {
                        int m = mx + 8*r, k = k0 + kkx;
                        rx[r] = g_ctxp[0][m*P_ + k] + g_ctxp[1][m*P_ + k];
                    }
                } else {
                    #pragma unroll
                    for (int r = 0; r < 8; r++) {
                        int m = mx + 8*r, k = k0 + kkx - P_;
                        rx[r] = g_h1[m*H_ + k];
                    }
                }
            };
            auto loadW = [&](int k0) {
                #pragma unroll
                for (int r = 0; r < 8; r++) {
                    int k = k0 + kw + 4*r;
                    rw[r] = (k < P_) ? Wih1[(size_t)(E_ + k) * G1 + c0col + cw]
                                     : Whh1[(size_t)(k - P_) * G1 + c0col + cw];
                }
            };
            GEMM_DECL_ACC();
            loadX(kbase); loadW(kbase);
            for (int k0 = kbase; k0 < kbase + 192; k0 += 32) {
                #pragma unroll
                for (int r = 0; r < 8; r++) {
                    xs[kkx*68 + mx + 8*r] = rx[r];
                    ws[(kw + 4*r)*68 + cw] = rw[r];
                }
                __syncthreads();
                if (k0 + 32 < kbase + 192) { loadX(k0 + 32); loadW(k0 + 32); }
                #pragma unroll
                for (int kk = 0; kk < 32; kk++) {
                    float4 a  = *(const float4*)&xs[kk*68 + bg * 4];
                    float4 wv = *(const float4*)&ws[kk*68 + cg * 4];
                    GEMM_FMA16();
                }
                __syncthreads();
            }
            float accs[4][4] = {{acc00,acc01,acc02,acc03},{acc10,acc11,acc12,acc13},
                                {acc20,acc21,acc22,acc23},{acc30,acc31,acc32,acc33}};
            float* outp = g_gp1 + (size_t)ks * (B_ * G1);
            #pragma unroll
            for (int i = 0; i < 4; i++) {
                float4 r = make_float4(accs[i][0], accs[i][1], accs[i][2], accs[i][3]);
                *(float4*)&outp[(size_t)(bg*4 + i) * G1 + c0col + cg*4] = r;
            }
        }
        gbar();

        // ---------- P2: cell1 (all blocks) + logits(t-1) (blocks 64..127) ----------
        {
            int idx = bid * 256 + tid;
            int b = idx >> 9, u = idx & 511;
            int tok = (t == 0) ? 0 : y[b * T_ + (t - 1)];
            float G[4];
            #pragma unroll
            for (int g = 0; g < 4; g++) {
                int col = g * H_ + u;
                float s = g_embg[tok * G1 + col];
                #pragma unroll
                for (int ks = 0; ks < 4; ks++)
                    s += g_gp1[(size_t)ks * (B_*G1) + b * G1 + col];
                G[g] = s;
            }
            float c = g_c1[idx];
            float cn = sigf(G[1]) * c + sigf(G[0]) * tanhf(G[2]);
            g_c1[idx] = cn;
            g_h1[idx] = sigf(G[3]) * tanhf(cn);
        }
        if (t > 0 && bid >= 64) {
            int b = bid - 64;
            float* h2s  = sh;
            float* ctxs = sh + 256;
            h2s[tid]  = g_h2[pp][b * D_ + tid];
            ctxs[tid] = g_ctxp[0][b * P_ + tid] + g_ctxp[1][b * P_ + tid];
            __syncthreads();
            float4 o0 = *(const float4*)&h2s[lane*4];
            float4 o1 = *(const float4*)&h2s[128 + lane*4];
            float4 o2 = *(const float4*)&ctxs[lane*4];
            float4 o3 = *(const float4*)&ctxs[128 + lane*4];
            for (int v = w; v < V_; v += 8) {
                const float4* ev = (const float4*)(embW + (size_t)v * E_);
                float acc = dot4(o0, ev[lane]) + dot4(o1, ev[32+lane])
                          + dot4(o2, ev[64+lane]) + dot4(o3, ev[96+lane]);
                #pragma unroll
                for (int off = 16; off; off >>= 1) acc += __shfl_xor_sync(0xffffffffu, acc, off);
                if (lane == 0) pred[((size_t)b * T_ + (t-1)) * V_ + v] = acc + char_b[v];
            }
        }
        gbar();

        // ---------- P3: LSTM2 gemm partials (16 col-tiles x 8 K-slices of 96) ----------
        {
            int ct = bid >> 3, ks = bid & 7;
            int c0col = ct * 64;
            int kbase = ks * 96;
            const float* __restrict__ h2old = g_h2[pp];
            float rx[8], rw[8];
            auto loadX = [&](int k0) {
                if (k0 < H_) {
                    #pragma unroll
                    for (int r = 0; r < 8; r++) {
                        int m = mx + 8*r, k = k0 + kkx;
                        rx[r] = g_h1[m*H_ + k];
                    }
                } else {
                    #pragma unroll
                    for (int r = 0; r < 8; r++) {
                        int m = mx + 8*r, k = k0 + kkx - H_;
                        rx[r] = h2old[m*D_ + k];
                    }
                }
            };
            auto loadW = [&](int k0) {
                #pragma unroll
                for (int r = 0; r < 8; r++) {
                    int k = k0 + kw + 4*r;
                    rw[r] = (k < H_) ? Wih2[(size_t)k * G2 + c0col + cw]
                                     : Whh2[(size_t)(k - H_) * G2 + c0col + cw];
                }
            };
            GEMM_DECL_ACC();
            loadX(kbase); loadW(kbase);
            for (int k0 = kbase; k0 < kbase + 96; k0 += 32) {
                #pragma unroll
                for (int r = 0; r < 8; r++) {
                    xs[kkx*68 + mx + 8*r] = rx[r];
                    ws[(kw + 4*r)*68 + cw] = rw[r];
                }
                __syncthreads();
                if (k0 + 32 < kbase + 96) { loadX(k0 + 32); loadW(k0 + 32); }
                #pragma unroll
                for (int kk = 0; kk < 32; kk++) {
                    float4 a  = *(const float4*)&xs[kk*68 + bg * 4];
                    float4 wv = *(const float4*)&ws[kk*68 + cg * 4];
                    GEMM_FMA16();
                }
                __syncthreads();
            }
            float accs[4][4] = {{acc00,acc01,acc02,acc03},{acc10,acc11,acc12,acc13},
                                {acc20,acc21,acc22,acc23},{acc30,acc31,acc32,acc33}};
            float* outp = g_gp2 + (size_t)ks * (B_ * G2);
            #pragma unroll
            for (int i = 0; i < 4; i++) {
                float4 r = make_float4(accs[i][0], accs[i][1], accs[i][2], accs[i][3]);
                *(float4*)&outp[(size_t)(bg*4 + i) * G2 + c0col + cg*4] = r;
            }
        }
        gbar();

        // ---------- P4: cell2 (pairwise redundant) + scores (half-S per block) ----------
        {
            int b = bid >> 1, half = bid & 1;
            float* h2s = sh;
            // cell2
            {
                int u = tid;
                float G[4];
                #pragma unroll
                for (int g = 0; g < 4; g++) {
                    int col = g * D_ + u;
                    float s = bih2[col] + bhh2[col];
                    #pragma unroll
                    for (int ks = 0; ks < 8; ks++)
                        s += g_gp2[(size_t)ks * (B_*G2) + b * G2 + col];
                    G[g] = s;
                }
                int idx = b * D_ + u;
                float c = g_c2[pp][idx];
                float cn = sigf(G[1]) * c + sigf(G[0]) * tanhf(G[2]);
                g_c2[pp ^ 1][idx] = cn;                // both halves write identical values
                float hn = sigf(G[3]) * tanhf(cn);
                g_h2[pp ^ 1][idx] = hn;
                h2s[u] = hn;
            }
            __syncthreads();
            int len = lens[b];
            int base = half * 400;
            int smax = base + 400;
            float4 q0 = *(const float4*)&h2s[lane*4];
            float4 q1 = *(const float4*)&h2s[128 + lane*4];
            const float* __restrict__ kb = g_keyq + (size_t)b * S_ * D_;
            const float* __restrict__ kq = g_kbq + b * S_;
            for (int j = 0; j < 7; j++) {
                int s0 = base + j * 64 + w * 8;
                float a0=0,a1=0,a2=0,a3=0,a4=0,a5=0,a6=0,a7=0;
                #define SCORE1(i, ai)                                              \
                    if (s0 + i < len && s0 + i < smax) {                           \
                        const float4* p = (const float4*)(kb + (size_t)(s0+i) * D_); \
                        ai = dot4(q0, p[lane]) + dot4(q1, p[32 + lane]);           \
                    }
                SCORE1(0,a0) SCORE1(1,a1) SCORE1(2,a2) SCORE1(3,a3)
                SCORE1(4,a4) SCORE1(5,a5) SCORE1(6,a6) SCORE1(7,a7)
                #undef SCORE1
                #pragma unroll
                for (int off = 16; off; off >>= 1) {
                    a0 += __shfl_xor_sync(0xffffffffu, a0, off);
                    a1 += __shfl_xor_sync(0xffffffffu, a1, off);
                    a2 += __shfl_xor_sync(0xffffffffu, a2, off);
                    a3 += __shfl_xor_sync(0xffffffffu, a3, off);
                    a4 += __shfl_xor_sync(0xffffffffu, a4, off);
                    a5 += __shfl_xor_sync(0xffffffffu, a5, off);
                    a6 += __shfl_xor_sync(0xffffffffu, a6, off);
                    a7 += __shfl_xor_sync(0xffffffffu, a7, off);
                }
                if (lane < 8) {
                    int s = s0 + lane;
                    if (s < smax) {
                        float v = (lane==0)?a0:(lane==1)?a1:(lane==2)?a2:(lane==3)?a3
                                 :(lane==4)?a4:(lane==5)?a5:(lane==6)?a6:a7;
                        g_sc[b * S_ + s] = (s < len) ? v + kq[s] : -1e9f;
                    }
                }
            }
        }
        gbar();

        // ---------- P5: softmax (redundant per pair) + context half + plot ----------
        {
            int b = bid >> 1, half = bid & 1;
            float* sc  = sh;            // 800
            float* red = sh + 800;      // 256
            float4* red4 = (float4*)(sh + 1056);  // 256 float4
            for (int s = tid; s < S_; s += 256) sc[s] = g_sc[b * S_ + s];
            __syncthreads();
            float mx2 = -3.4e38f;
            for (int s = tid; s < S_; s += 256) mx2 = fmaxf(mx2, sc[s]);
            red[tid] = mx2; __syncthreads();
            for (int off = 128; off; off >>= 1) { if (tid < off) red[tid] = fmaxf(red[tid], red[tid+off]); __syncthreads(); }
            float M = red[0];
            __syncthreads();
            float sm = 0.f;
            for (int s = tid; s < S_; s += 256) { float e = __expf(sc[s] - M); sc[s] = e; sm += e; }
            red[tid] = sm; __syncthreads();
            for (int off = 128; off; off >>= 1) { if (tid < off) red[tid] += red[tid+off]; __syncthreads(); }
            float inv = 1.f / red[0];
            __syncthreads();
            // context over this block's s-half
            {
                int len = lens[b];
                int sl = tid >> 6, p4i = tid & 63;
                int sbeg = half * 400 + sl * 100;
                int send = sbeg + 100; if (send > len) send = len;
                const float4* __restrict__ vp = (const float4*)(g_val + (size_t)b * S_ * P_) + p4i;
                float4 acc = make_float4(0.f, 0.f, 0.f, 0.f);
                int s = sbeg;
                for (; s + 4 <= send; s += 4) {
                    float w0 = sc[s], w1 = sc[s+1], w2 = sc[s+2], w3 = sc[s+3];
                    float4 v0 = vp[(size_t)s * 64];
                    float4 v1 = vp[(size_t)(s+1) * 64];
                    float4 v2 = vp[(size_t)(s+2) * 64];
                    float4 v3 = vp[(size_t)(s+3) * 64];
                    acc.x += w0*v0.x + w1*v1.x + w2*v2.x + w3*v3.x;
                    acc.y += w0*v0.y + w1*v1.y + w2*v2.y + w3*v3.y;
                    acc.z += w0*v0.z + w1*v1.z + w2*v2.z + w3*v3.z;
                    acc.w += w0*v0.w + w1*v1.w + w2*v2.w + w3*v3.w;
                }
                for (; s < send; s++) {
                    float wgt = sc[s];
                    float4 v = vp[(size_t)s * 64];
                    acc.x += wgt*v.x; acc.y += wgt*v.y; acc.z += wgt*v.z; acc.w += wgt*v.w;
                }
                red4[tid] = acc;
            }
            __syncthreads();
            if (tid < 64) {
                float4 a = red4[tid], b1 = red4[64+tid], c1 = red4[128+tid], d1 = red4[192+tid];
                float4 r = make_float4((a.x+b1.x+c1.x+d1.x)*inv, (a.y+b1.y+c1.y+d1.y)*inv,
                                       (a.z+b1.z+c1.z+d1.z)*inv, (a.w+b1.w+c1.w+d1.w)*inv);
                *(float4*)&g_ctxp[half][b * P_ + tid*4] = r;
            }
            if (bid == 0) {
                for (int s = tid; s < S_; s += 256) plot[s * T_ + t] = sc[s] * inv;
            }
        }
        gbar();
    }

    // ---------- final logits for t = T-1 ----------
    if (bid >= 64) {
        int b = bid - 64;
        int slot = ((T_ - 1) & 1) ^ 1;
        float* h2s  = sh;
        float* ctxs = sh + 256;
        h2s[tid]  = g_h2[slot][b * D_ + tid];
        ctxs[tid] = g_ctxp[0][b * P_ + tid] + g_ctxp[1][b * P_ + tid];
        __syncthreads();
        float4 o0 = *(const float4*)&h2s[lane*4];
        float4 o1 = *(const float4*)&h2s[128 + lane*4];
        float4 o2 = *(const float4*)&ctxs[lane*4];
        float4 o3 = *(const float4*)&ctxs[128 + lane*4];
        for (int v = w; v < V_; v += 8) {
            const float4* ev = (const float4*)(embW + (size_t)v * E_);
            float acc = dot4(o0, ev[lane]) + dot4(o1, ev[32+lane])
                      + dot4(o2, ev[64+lane]) + dot4(o3, ev[96+lane]);
            #pragma unroll
            for (int off = 16; off; off >>= 1) acc += __shfl_xor_sync(0xffffffffu, acc, off);
            if (lane == 0) pred[((size_t)b * T_ + (T_-1)) * V_ + v] = acc + char_b[v];
        }
    }
}

// ---------------- launch: ONE node -----------------------------------------
extern "C" void kernel_launch(void* const* d_in, const int* in_sizes, int n_in,
                              void* d_out, int out_size) {
    const float* enc    = (const float*)d_in[0];
    const float* embW   = (const float*)d_in[1];
    const float* Wih1   = (const float*)d_in[2];
    const float* bih1   = (const float*)d_in[3];
    const float* Whh1   = (const float*)d_in[4];
    const float* bhh1   = (const float*)d_in[5];
    const float* Wih2   = (const float*)d_in[6];
    const float* bih2   = (const float*)d_in[7];
    const float* Whh2   = (const float*)d_in[8];
    const float* bhh2   = (const float*)d_in[9];
    const float* Wk     = (const float*)d_in[10];
    const float* bk     = (const float*)d_in[11];
    const float* Wv     = (const float*)d_in[12];
    const float* bv     = (const float*)d_in[13];
    const float* Wq     = (const float*)d_in[14];
    const float* bq     = (const float*)d_in[15];
    const float* char_b = (const float*)d_in[16];
    const int*   lens   = (const int*)d_in[17];
    const int*   y      = (const int*)d_in[18];

    float* pred = (float*)d_out;                 // (B, T, V)
    float* plot = pred + (size_t)B_ * T_ * V_;   // (S, T)

    persist_kernel<<<NBLK, 256>>>(enc, embW, Wih1, bih1, Whh1, bhh1,
                                  Wih2, bih2, Whh2, bhh2,
                                  Wk, bk, Wv, bv, Wq, bq,
                                  char_b, lens, y, pred, plot);
}

// round 6
// speedup vs baseline: 8.2300x; 1.2137x over previous
#include <cuda_runtime.h>
#include <math.h>

#define B_   64
#define S_   800
#define ENC_ 512
#define T_   250
#define V_   30
#define E_   512
#define H_   512
#define D_   256
#define P_   256
#define NBLK 128
#define NTHR 512
#define G1   (4*H_)
#define G2   (4*D_)

// ---------------- device scratch ----------------
__device__ float g_val [B_*S_*P_];       // val_proj (B,S,P)
__device__ float g_keyq[B_*S_*D_];       // scale * key_proj @ Wq^T  (B,S,D)
__device__ float g_kbq [B_*S_];          // scale * key_proj . bq
__device__ float g_embg[V_*G1];          // embW@Wih1[0:512] + bih1 + bhh1
__device__ float g_wfold[ENC_*D_];       // scale * Wk @ Wq^T
__device__ float g_bfold[D_];
__device__ float g_wb[ENC_];
__device__ float g_c0[1];
__device__ float g_h1[B_*H_];
__device__ float g_c1[B_*H_];
__device__ float g_h2[B_*D_];            // single buffer (one writer block per batch)
__device__ float g_c2[B_*D_];
__device__ float g_ctx[B_*P_];
__device__ float g_gp1[8*B_*G1];         // lstm1 gate partials (8 K-slices)
__device__ float g_gp2[8*B_*G2];         // lstm2 gate partials (8 K-slices)

__device__ unsigned g_bar_count;         // zero-init; returns to 0 each barrier
__device__ unsigned g_bar_gen;

__device__ __forceinline__ void gbar() {
    __syncthreads();
    if (threadIdx.x == 0) {
        unsigned gen = *(volatile unsigned*)&g_bar_gen;
        __threadfence();
        if (atomicAdd(&g_bar_count, 1u) == NBLK - 1u) {
            g_bar_count = 0u;
            __threadfence();
            *(volatile unsigned*)&g_bar_gen = gen + 1u;
        } else {
            while (*(volatile unsigned*)&g_bar_gen == gen) __nanosleep(16);
            __threadfence();
        }
    }
    __syncthreads();
}

// half-block barrier (256 threads): barrier id 1 for half 0, id 2 for half 1
__device__ __forceinline__ void hbar(int half) {
    asm volatile("bar.sync %0, 256;" :: "r"(half + 1) : "memory");
}

__device__ __forceinline__ float sigf(float x) { return 1.0f / (1.0f + expf(-x)); }
__device__ __forceinline__ float dot4(float4 a, float4 b) {
    return a.x*b.x + a.y*b.y + a.z*b.z + a.w*b.w;
}

#define GEMM_FMA16()                                             \
    do {                                                          \
        acc00 += a.x*wv.x; acc01 += a.x*wv.y; acc02 += a.x*wv.z; acc03 += a.x*wv.w; \
        acc10 += a.y*wv.x; acc11 += a.y*wv.y; acc12 += a.y*wv.z; acc13 += a.y*wv.w; \
        acc20 += a.z*wv.x; acc21 += a.z*wv.y; acc22 += a.z*wv.z; acc23 += a.z*wv.w; \
        acc30 += a.w*wv.x; acc31 += a.w*wv.y; acc32 += a.w*wv.z; acc33 += a.w*wv.w; \
    } while (0)

#define GEMM_DECL_ACC()                                          \
    float acc00=0,acc01=0,acc02=0,acc03=0, acc10=0,acc11=0,acc12=0,acc13=0, \
          acc20=0,acc21=0,acc22=0,acc23=0, acc30=0,acc31=0,acc32=0,acc33=0

// ================== the ONE kernel ==================
__global__ void __launch_bounds__(NTHR, 1)
persist_kernel(const float* __restrict__ enc,  const float* __restrict__ embW,
               const float* __restrict__ Wih1, const float* __restrict__ bih1,
               const float* __restrict__ Whh1, const float* __restrict__ bhh1,
               const float* __restrict__ Wih2, const float* __restrict__ bih2,
               const float* __restrict__ Whh2, const float* __restrict__ bhh2,
               const float* __restrict__ Wk,   const float* __restrict__ bk,
               const float* __restrict__ Wv,   const float* __restrict__ bv,
               const float* __restrict__ Wq,   const float* __restrict__ bq,
               const float* __restrict__ char_b,
               const int* __restrict__ lens,   const int* __restrict__ y,
               float* __restrict__ pred,       float* __restrict__ plot)
{
    __shared__ __align__(16) float sh[8704];     // two 4352-float half-arenas
    const int tid  = threadIdx.x;
    const int bid  = blockIdx.x;
    const int half = tid >> 8;
    const int htid = tid & 255;
    const int vb   = bid * 2 + half;             // virtual half-block id (0..255)
    float* xs = sh + half * 4352;                // [32][68]
    float* ws = xs + 2176;                       // [32][68]
    const int cg = htid & 15, bg = htid >> 4;
    const int kkx = htid & 31, mx = htid >> 5;
    const int cw  = htid & 63, kw = htid >> 6;
    const int w = tid >> 5, lane = tid & 31;     // whole-block warp index (0..15)
    const float scl = 0.0625f;                   // 1/sqrt(256)

    // ============ PHASE A: weight folds, embg table, state init ============
    if (vb < 32) {
        // wfold tile: scale * Wk @ Wq^T
        int n0 = (vb & 3) * 64, m0 = (vb >> 2) * 64;
        GEMM_DECL_ACC();
        for (int k0 = 0; k0 < P_; k0 += 32) {
            #pragma unroll
            for (int e = htid; e < 2048; e += 256) {
                int kk = e & 31, m = e >> 5;
                xs[kk*68 + m] = Wk[(m0 + m) * P_ + k0 + kk];
            }
            #pragma unroll
            for (int e = htid; e < 2048; e += 256) {
                int kk = e & 31, h = e >> 5;
                ws[kk*68 + h] = Wq[(n0 + h) * P_ + k0 + kk];
            }
            hbar(half);
            #pragma unroll
            for (int kk = 0; kk < 32; kk++) {
                float4 a  = *(const float4*)&xs[kk*68 + bg * 4];
                float4 wv = *(const float4*)&ws[kk*68 + cg * 4];
                GEMM_FMA16();
            }
            hbar(half);
        }
        float accs[4][4] = {{acc00,acc01,acc02,acc03},{acc10,acc11,acc12,acc13},
                            {acc20,acc21,acc22,acc23},{acc30,acc31,acc32,acc33}};
        #pragma unroll
        for (int i = 0; i < 4; i++) {
            float4 r = make_float4(accs[i][0]*scl, accs[i][1]*scl, accs[i][2]*scl, accs[i][3]*scl);
            *(float4*)&g_wfold[(size_t)(m0 + bg*4 + i) * D_ + n0 + cg*4] = r;
        }
    } else if (vb < 34) {
        int e = (vb - 32) * 256 + htid;
        float a = 0.f;
        for (int p = 0; p < P_; p++) a += Wk[e * P_ + p] * bq[p];
        g_wb[e] = a * scl;
    } else if (vb == 34) {
        float a = 0.f;
        for (int p = 0; p < P_; p++) a += bk[p] * Wq[htid * P_ + p];
        g_bfold[htid] = a * scl;
        if (htid == 0) {
            float c = 0.f;
            for (int p = 0; p < P_; p++) c += bk[p] * bq[p];
            g_c0[0] = c * scl;
        }
    } else if (vb < 65) {
        // embg for v = vb - 35 (0..29)
        int v = vb - 35;
        float* es = xs;
        es[htid] = embW[v * E_ + htid];
        es[htid + 256] = embW[v * E_ + 256 + htid];
        hbar(half);
        float acc[8];
        #pragma unroll
        for (int r = 0; r < 8; r++) {
            int g = htid + 256 * r;
            acc[r] = bih1[g] + bhh1[g];
        }
        for (int e = 0; e < E_; e++) {
            float ev = es[e];
            const float* wr = Wih1 + (size_t)e * G1 + htid;
            #pragma unroll
            for (int r = 0; r < 8; r++) acc[r] += ev * wr[256 * r];
        }
        #pragma unroll
        for (int r = 0; r < 8; r++) g_embg[v * G1 + htid + 256 * r] = acc[r];
    } else if (vb >= 192) {
        // state init for batch b = vb - 192
        int b = vb - 192;
        for (int j = htid; j < H_; j += 256) { g_h1[b*H_ + j] = 0.f; g_c1[b*H_ + j] = 0.f; }
        g_h2[b*D_ + htid] = 0.f; g_c2[b*D_ + htid] = 0.f;
        float* es = xs;
        es[htid] = enc[(size_t)b * S_ * ENC_ + htid];
        es[htid + 256] = enc[(size_t)b * S_ * ENC_ + 256 + htid];
        hbar(half);
        float acc = bk[htid];
        #pragma unroll 4
        for (int k = 0; k < ENC_; k++) acc += es[k] * Wk[k * P_ + htid];
        g_ctx[b*P_ + htid] = acc;
    }
    gbar();

    // ============ PHASE B: main precompute GEMM + kbq ============
    {
        // out(51200 x 512) = enc @ [Wv | Wfold]; 6400 tiles over 256 vblocks
        for (int q = 0; q < 25; q++) {
            int tt = vb + 256 * q;
            int n0 = (tt & 7) * 64, m0 = (tt >> 3) * 64;
            bool isval = (n0 < P_);
            const float* __restrict__ Bsrc = isval ? (Wv + n0) : (g_wfold + (n0 - P_));
            GEMM_DECL_ACC();
            for (int k0 = 0; k0 < ENC_; k0 += 32) {
                #pragma unroll
                for (int e = htid; e < 2048; e += 256) {
                    int kk = e & 31, m = e >> 5;
                    xs[kk*68 + m] = enc[(size_t)(m0 + m) * ENC_ + k0 + kk];
                }
                #pragma unroll
                for (int e = htid; e < 2048; e += 256) {
                    int c = e & 63, kk = e >> 6;
                    ws[kk*68 + c] = Bsrc[(size_t)(k0 + kk) * P_ + c];
                }
                hbar(half);
                #pragma unroll
                for (int kk = 0; kk < 32; kk++) {
                    float4 a  = *(const float4*)&xs[kk*68 + bg * 4];
                    float4 wv = *(const float4*)&ws[kk*68 + cg * 4];
                    GEMM_FMA16();
                }
                hbar(half);
            }
            float4 bias = isval ? *(const float4*)&bv[n0 + cg*4]
                                : *(const float4*)&g_bfold[n0 - P_ + cg*4];
            float* __restrict__ outp = isval ? g_val : g_keyq;
            int colbase = isval ? n0 : (n0 - P_);
            float accs[4][4] = {{acc00,acc01,acc02,acc03},{acc10,acc11,acc12,acc13},
                                {acc20,acc21,acc22,acc23},{acc30,acc31,acc32,acc33}};
            #pragma unroll
            for (int i = 0; i < 4; i++) {
                float4 r = make_float4(accs[i][0]+bias.x, accs[i][1]+bias.y,
                                       accs[i][2]+bias.z, accs[i][3]+bias.w);
                *(float4*)&outp[(size_t)(m0 + bg*4 + i) * P_ + colbase + cg*4] = r;
            }
        }
        // kbq: 200 rows per vblock
        hbar(half);
        float* wbs = xs;
        wbs[htid] = g_wb[htid]; wbs[256 + htid] = g_wb[256 + htid];
        hbar(half);
        int hl = htid & 31, hw = htid >> 5;
        float4 w0 = *(const float4*)&wbs[hl*4];
        float4 w1 = *(const float4*)&wbs[128 + hl*4];
        float4 w2 = *(const float4*)&wbs[256 + hl*4];
        float4 w3 = *(const float4*)&wbs[384 + hl*4];
        float c0 = g_c0[0];
        int r0 = vb * 200 + hw * 25;
        for (int i = 0; i < 25; i++) {
            int row = r0 + i;
            const float4* ep = (const float4*)(enc + (size_t)row * ENC_);
            float acc = dot4(ep[hl], w0) + dot4(ep[32+hl], w1)
                      + dot4(ep[64+hl], w2) + dot4(ep[96+hl], w3);
            #pragma unroll
            for (int off = 16; off; off >>= 1) acc += __shfl_xor_sync(0xffffffffu, acc, off);
            if (hl == 0) g_kbq[row] = acc + c0;
        }
    }
    gbar();

    // ============ DECODE LOOP (4 grid barriers / step) ============
    for (int t = 0; t < T_; t++) {

        // ---------- P1: LSTM1 gemm partials (32 col-tiles x 8 K-slices of 96) ----------
        {
            int ct = vb >> 3, ks = vb & 7;
            int c0col = ct * 64;
            int kbase = ks * 96;
            float rx[8], rw[8];
            auto loadX = [&](int k0) {
                if (k0 < P_) {
                    #pragma unroll
                    for (int r = 0; r < 8; r++)
                        rx[r] = g_ctx[(mx + 8*r) * P_ + k0 + kkx];
                } else {
                    #pragma unroll
                    for (int r = 0; r < 8; r++)
                        rx[r] = g_h1[(mx + 8*r) * H_ + k0 + kkx - P_];
                }
            };
            auto loadW = [&](int k0) {
                #pragma unroll
                for (int r = 0; r < 8; r++) {
                    int k = k0 + kw + 4*r;
                    rw[r] = (k < P_) ? Wih1[(size_t)(E_ + k) * G1 + c0col + cw]
                                     : Whh1[(size_t)(k - P_) * G1 + c0col + cw];
                }
            };
            GEMM_DECL_ACC();
            loadX(kbase); loadW(kbase);
            for (int k0 = kbase; k0 < kbase + 96; k0 += 32) {
                #pragma unroll
                for (int r = 0; r < 8; r++) {
                    xs[kkx*68 + mx + 8*r] = rx[r];
                    ws[(kw + 4*r)*68 + cw] = rw[r];
                }
                hbar(half);
                if (k0 + 32 < kbase + 96) { loadX(k0 + 32); loadW(k0 + 32); }
                #pragma unroll
                for (int kk = 0; kk < 32; kk++) {
                    float4 a  = *(const float4*)&xs[kk*68 + bg * 4];
                    float4 wv = *(const float4*)&ws[kk*68 + cg * 4];
                    GEMM_FMA16();
                }
                hbar(half);
            }
            float accs[4][4] = {{acc00,acc01,acc02,acc03},{acc10,acc11,acc12,acc13},
                                {acc20,acc21,acc22,acc23},{acc30,acc31,acc32,acc33}};
            float* outp = g_gp1 + (size_t)ks * (B_ * G1);
            #pragma unroll
            for (int i = 0; i < 4; i++) {
                float4 r = make_float4(accs[i][0], accs[i][1], accs[i][2], accs[i][3]);
                *(float4*)&outp[(size_t)(bg*4 + i) * G1 + c0col + cg*4] = r;
            }
        }
        gbar();

        // ---------- P2: cell1 (blocks 0-63) + logits(t-1) (blocks 64-127) ----------
        if (bid < 64) {
            int idx = bid * NTHR + tid;
            int b = idx >> 9, u = idx & 511;
            int tok = (t == 0) ? 0 : y[b * T_ + (t - 1)];
            float G[4];
            #pragma unroll
            for (int g = 0; g < 4; g++) {
                int col = g * H_ + u;
                float s = g_embg[tok * G1 + col];
                #pragma unroll
                for (int ks = 0; ks < 8; ks++)
                    s += g_gp1[(size_t)ks * (B_*G1) + b * G1 + col];
                G[g] = s;
            }
            float c = g_c1[idx];
            float cn = sigf(G[1]) * c + sigf(G[0]) * tanhf(G[2]);
            g_c1[idx] = cn;
            g_h1[idx] = sigf(G[3]) * tanhf(cn);
        } else if (t > 0) {
            int b = bid - 64;
            float* h2s  = sh;
            float* ctxs = sh + 256;
            if (tid < 256) {
                h2s[tid]  = g_h2[b * D_ + tid];
                ctxs[tid] = g_ctx[b * P_ + tid];
            }
            __syncthreads();
            float4 o0 = *(const float4*)&h2s[lane*4];
            float4 o1 = *(const float4*)&h2s[128 + lane*4];
            float4 o2 = *(const float4*)&ctxs[lane*4];
            float4 o3 = *(const float4*)&ctxs[128 + lane*4];
            for (int v = w; v < V_; v += 16) {
                const float4* ev = (const float4*)(embW + (size_t)v * E_);
                float acc = dot4(o0, ev[lane]) + dot4(o1, ev[32+lane])
                          + dot4(o2, ev[64+lane]) + dot4(o3, ev[96+lane]);
                #pragma unroll
                for (int off = 16; off; off >>= 1) acc += __shfl_xor_sync(0xffffffffu, acc, off);
                if (lane == 0) pred[((size_t)b * T_ + (t-1)) * V_ + v] = acc + char_b[v];
            }
        }
        gbar();

        // ---------- P3: LSTM2 gemm partials (16 col-tiles x 8 K-slices; half 0 of every block) ----------
        if (half == 0) {
            int ct = bid >> 3, ks = bid & 7;
            int c0col = ct * 64;
            int kbase = ks * 96;
            float rx[8], rw[8];
            auto loadX = [&](int k0) {
                if (k0 < H_) {
                    #pragma unroll
                    for (int r = 0; r < 8; r++)
                        rx[r] = g_h1[(mx + 8*r) * H_ + k0 + kkx];
                } else {
                    #pragma unroll
                    for (int r = 0; r < 8; r++)
                        rx[r] = g_h2[(mx + 8*r) * D_ + k0 + kkx - H_];
                }
            };
            auto loadW = [&](int k0) {
                #pragma unroll
                for (int r = 0; r < 8; r++) {
                    int k = k0 + kw + 4*r;
                    rw[r] = (k < H_) ? Wih2[(size_t)k * G2 + c0col + cw]
                                     : Whh2[(size_t)(k - H_) * G2 + c0col + cw];
                }
            };
            GEMM_DECL_ACC();
            loadX(kbase); loadW(kbase);
            for (int k0 = kbase; k0 < kbase + 96; k0 += 32) {
                #pragma unroll
                for (int r = 0; r < 8; r++) {
                    xs[kkx*68 + mx + 8*r] = rx[r];
                    ws[(kw + 4*r)*68 + cw] = rw[r];
                }
                hbar(0);
                if (k0 + 32 < kbase + 96) { loadX(k0 + 32); loadW(k0 + 32); }
                #pragma unroll
                for (int kk = 0; kk < 32; kk++) {
                    float4 a  = *(const float4*)&xs[kk*68 + bg * 4];
                    float4 wv = *(const float4*)&ws[kk*68 + cg * 4];
                    GEMM_FMA16();
                }
                hbar(0);
            }
            float accs[4][4] = {{acc00,acc01,acc02,acc03},{acc10,acc11,acc12,acc13},
                                {acc20,acc21,acc22,acc23},{acc30,acc31,acc32,acc33}};
            float* outp = g_gp2 + (size_t)ks * (B_ * G2);
            #pragma unroll
            for (int i = 0; i < 4; i++) {
                float4 r = make_float4(accs[i][0], accs[i][1], accs[i][2], accs[i][3]);
                *(float4*)&outp[(size_t)(bg*4 + i) * G2 + c0col + cg*4] = r;
            }
        }
        gbar();

        // ---------- P4: cell2 + scores + softmax + context (block per batch) ----------
        if (bid < B_) {
            int b = bid;
            float* h2s = sh;                       // 256
            float* sc  = sh + 256;                 // 800
            float* red = sh + 1056;                // 512
            float4* red4 = (float4*)(sh + 1568);   // 512 float4 (8192B)
            // cell2
            if (tid < 256) {
                int u = tid;
                float G[4];
                #pragma unroll
                for (int g = 0; g < 4; g++) {
                    int col = g * D_ + u;
                    float s = bih2[col] + bhh2[col];
                    #pragma unroll
                    for (int ks = 0; ks < 8; ks++)
                        s += g_gp2[(size_t)ks * (B_*G2) + b * G2 + col];
                    G[g] = s;
                }
                int idx = b * D_ + u;
                float c = g_c2[idx];
                float cn = sigf(G[1]) * c + sigf(G[0]) * tanhf(G[2]);
                g_c2[idx] = cn;
                float hn = sigf(G[3]) * tanhf(cn);
                g_h2[idx] = hn;
                h2s[u] = hn;
            }
            __syncthreads();
            int len = lens[b];
            // scores: 16 warps x 50 consecutive positions
            {
                float4 q0 = *(const float4*)&h2s[lane*4];
                float4 q1 = *(const float4*)&h2s[128 + lane*4];
                const float* __restrict__ kb = g_keyq + (size_t)b * S_ * D_;
                const float* __restrict__ kq = g_kbq + b * S_;
                int base = w * 50;
                int bend = base + 50;
                for (int j = 0; j < 7; j++) {
                    int s0 = base + j * 8;
                    float a0=0,a1=0,a2=0,a3=0,a4=0,a5=0,a6=0,a7=0;
                    #define SCORE1(i, ai)                                              \
                        if (s0 + i < bend && s0 + i < len) {                           \
                            const float4* p = (const float4*)(kb + (size_t)(s0+i) * D_); \
                            ai = dot4(q0, p[lane]) + dot4(q1, p[32 + lane]);           \
                        }
                    SCORE1(0,a0) SCORE1(1,a1) SCORE1(2,a2) SCORE1(3,a3)
                    SCORE1(4,a4) SCORE1(5,a5) SCORE1(6,a6) SCORE1(7,a7)
                    #undef SCORE1
                    #pragma unroll
                    for (int off = 16; off; off >>= 1) {
                        a0 += __shfl_xor_sync(0xffffffffu, a0, off);
                        a1 += __shfl_xor_sync(0xffffffffu, a1, off);
                        a2 += __shfl_xor_sync(0xffffffffu, a2, off);
                        a3 += __shfl_xor_sync(0xffffffffu, a3, off);
                        a4 += __shfl_xor_sync(0xffffffffu, a4, off);
                        a5 += __shfl_xor_sync(0xffffffffu, a5, off);
                        a6 += __shfl_xor_sync(0xffffffffu, a6, off);
                        a7 += __shfl_xor_sync(0xffffffffu, a7, off);
                    }
                    if (lane < 8) {
                        int s = s0 + lane;
                        if (s < bend) {
                            float v = (lane==0)?a0:(lane==1)?a1:(lane==2)?a2:(lane==3)?a3
                                     :(lane==4)?a4:(lane==5)?a5:(lane==6)?a6:a7;
                            sc[s] = (s < len) ? v + kq[s] : -1e9f;
                        }
                    }
                }
            }
            __syncthreads();
            // softmax over sc[0..799] with 512 threads
            float mx2 = -3.4e38f;
            for (int s = tid; s < S_; s += NTHR) mx2 = fmaxf(mx2, sc[s]);
            red[tid] = mx2; __syncthreads();
            for (int off = 256; off; off >>= 1) { if (tid < off) red[tid] = fmaxf(red[tid], red[tid+off]); __syncthreads(); }
            float M = red[0];
            __syncthreads();
            float sm = 0.f;
            for (int s = tid; s < S_; s += NTHR) { float e = __expf(sc[s] - M); sc[s] = e; sm += e; }
            red[tid] = sm; __syncthreads();
            for (int off = 256; off; off >>= 1) { if (tid < off) red[tid] += red[tid+off]; __syncthreads(); }
            float inv = 1.f / red[0];
            __syncthreads();
            // context: 8 s-slices x 64 col-quads
            {
                int sl = tid >> 6, p4i = tid & 63;
                int sbeg = sl * 100;
                int send = sbeg + 100; if (send > len) send = len;
                const float4* __restrict__ vp = (const float4*)(g_val + (size_t)b * S_ * P_) + p4i;
                float4 acc = make_float4(0.f, 0.f, 0.f, 0.f);
                int s = sbeg;
                for (; s + 4 <= send; s += 4) {
                    float w0 = sc[s], w1 = sc[s+1], w2 = sc[s+2], w3 = sc[s+3];
                    float4 v0 = vp[(size_t)s * 64];
                    float4 v1 = vp[(size_t)(s+1) * 64];
                    float4 v2 = vp[(size_t)(s+2) * 64];
                    float4 v3 = vp[(size_t)(s+3) * 64];
                    acc.x += w0*v0.x + w1*v1.x + w2*v2.x + w3*v3.x;
                    acc.y += w0*v0.y + w1*v1.y + w2*v2.y + w3*v3.y;
                    acc.z += w0*v0.z + w1*v1.z + w2*v2.z + w3*v3.z;
                    acc.w += w0*v0.w + w1*v1.w + w2*v2.w + w3*v3.w;
                }
                for (; s < send; s++) {
                    float wgt = sc[s];
                    float4 v = vp[(size_t)s * 64];
                    acc.x += wgt*v.x; acc.y += wgt*v.y; acc.z += wgt*v.z; acc.w += wgt*v.w;
                }
                red4[tid] = acc;
            }
            __syncthreads();
            if (tid < 64) {
                float4 r = make_float4(0.f, 0.f, 0.f, 0.f);
                #pragma unroll
                for (int i = 0; i < 8; i++) {
                    float4 v = red4[tid + 64 * i];
                    r.x += v.x; r.y += v.y; r.z += v.z; r.w += v.w;
                }
                r.x *= inv; r.y *= inv; r.z *= inv; r.w *= inv;
                *(float4*)&g_ctx[b * P_ + tid*4] = r;
            }
            if (bid == 0) {
                for (int s = tid; s < S_; s += NTHR) plot[s * T_ + t] = sc[s] * inv;
            }
        }
        gbar();
    }

    // ---------- final logits for t = T-1 ----------
    if (bid >= 64) {
        int b = bid - 64;
        float* h2s  = sh;
        float* ctxs = sh + 256;
        if (tid < 256) {
            h2s[tid]  = g_h2[b * D_ + tid];
            ctxs[tid] = g_ctx[b * P_ + tid];
        }
        __syncthreads();
        float4 o0 = *(const float4*)&h2s[lane*4];
        float4 o1 = *(const float4*)&h2s[128 + lane*4];
        float4 o2 = *(const float4*)&ctxs[lane*4];
        float4 o3 = *(const float4*)&ctxs[128 + lane*4];
        for (int v = w; v < V_; v += 16) {
            const float4* ev = (const float4*)(embW + (size_t)v * E_);
            float acc = dot4(o0, ev[lane]) + dot4(o1, ev[32+lane])
                      + dot4(o2, ev[64+lane]) + dot4(o3, ev[96+lane]);
            #pragma unroll
            for (int off = 16; off; off >>= 1) acc += __shfl_xor_sync(0xffffffffu, acc, off);
            if (lane == 0) pred[((size_t)b * T_ + (T_-1)) * V_ + v] = acc + char_b[v];
        }
    }
}

// ---------------- launch: ONE node -----------------------------------------
extern "C" void kernel_launch(void* const* d_in, const int* in_sizes, int n_in,
                              void* d_out, int out_size) {
    const float* enc    = (const float*)d_in[0];
    const float* embW   = (const float*)d_in[1];
    const float* Wih1   = (const float*)d_in[2];
    const float* bih1   = (const float*)d_in[3];
    const float* Whh1   = (const float*)d_in[4];
    const float* bhh1   = (const float*)d_in[5];
    const float* Wih2   = (const float*)d_in[6];
    const float* bih2   = (const float*)d_in[7];
    const float* Whh2   = (const float*)d_in[8];
    const float* bhh2   = (const float*)d_in[9];
    const float* Wk     = (const float*)d_in[10];
    const float* bk     = (const float*)d_in[11];
    const float* Wv     = (const float*)d_in[12];
    const float* bv     = (const float*)d_in[13];
    const float* Wq     = (const float*)d_in[14];
    const float* bq     = (const float*)d_in[15];
    const float* char_b = (const float*)d_in[16];
    const int*   lens   = (const int*)d_in[17];
    const int*   y      = (const int*)d_in[18];

    float* pred = (float*)d_out;                 // (B, T, V)
    float* plot = pred + (size_t)B_ * T_ * V_;   // (S, T)

    persist_kernel<<<NBLK, NTHR>>>(enc, embW, Wih1, bih1, Whh1, bhh1,
                                   Wih2, bih2, Whh2, bhh2,
                                   Wk, bk, Wv, bv, Wq, bq,
                                   char_b, lens, y, pred, plot);
}

// round 8
// speedup vs baseline: 10.4044x; 1.2642x over previous
#include <cuda_runtime.h>
#include <cuda_fp16.h>
#include <math.h>

#define B_   64
#define S_   800
#define ENC_ 512
#define T_   250
#define V_   30
#define E_   512
#define H_   512
#define D_   256
#define P_   256
#define NBLK 128
#define NTHR 512
#define G1   (4*H_)
#define G2   (4*D_)

// ---------------- device scratch ----------------
__device__ __align__(16) __half g_valh [B_*S_*P_];   // val_proj fp16
__device__ __align__(16) __half g_keyqh[B_*S_*D_];   // folded key fp16
__device__ float g_kbq [B_*S_];
__device__ float g_embg[V_*G1];
__device__ float g_wfold[ENC_*D_];
__device__ float g_bfold[D_];
__device__ float g_wb[ENC_];
__device__ float g_c0[1];
__device__ float g_h1[B_*H_];
__device__ float g_c1[B_*H_];
__device__ float g_h2[B_*D_];
__device__ float g_c2[B_*D_];
__device__ float g_ctx[B_*P_];
__device__ float g_gp1[8][B_*G1];    // 0..3 ctx-part (phase A), 4..7 h1-part (phase D prev step)
__device__ float g_gp2[12][B_*G2];   // 0..7 Wih2 (phase C), 8..11 Whh2 (phase A)

__device__ unsigned g_bar_count;
__device__ unsigned g_bar_gen;

__device__ __forceinline__ void gbar() {
    __syncthreads();
    if (threadIdx.x == 0) {
        unsigned gen = *(volatile unsigned*)&g_bar_gen;
        __threadfence();
        if (atomicAdd(&g_bar_count, 1u) == NBLK - 1u) {
            g_bar_count = 0u;
            __threadfence();
            *(volatile unsigned*)&g_bar_gen = gen + 1u;
        } else {
            while (*(volatile unsigned*)&g_bar_gen == gen) __nanosleep(16);
            __threadfence();
        }
    }
    __syncthreads();
}

__device__ __forceinline__ void hbar(int half) {
    asm volatile("bar.sync %0, 256;" :: "r"(half + 1) : "memory");
}

__device__ __forceinline__ float sigf(float x) { return 1.0f / (1.0f + expf(-x)); }
__device__ __forceinline__ float dot4(float4 a, float4 b) {
    return a.x*b.x + a.y*b.y + a.z*b.z + a.w*b.w;
}

// ---------------- packed fp32x2 FMA ----------------
__device__ __forceinline__ unsigned long long pack2(float x, float y) {
    unsigned long long r; asm("mov.b64 %0, {%1, %2};" : "=l"(r) : "f"(x), "f"(y)); return r;
}
__device__ __forceinline__ float2 unpack2(unsigned long long v) {
    float2 f; asm("mov.b64 {%0, %1}, %2;" : "=f"(f.x), "=f"(f.y) : "l"(v)); return f;
}
__device__ __forceinline__ void ffma2(unsigned long long& acc, unsigned long long a, unsigned long long b) {
    asm("fma.rn.f32x2 %0, %1, %2, %0;" : "+l"(acc) : "l"(a), "l"(b));
}

#define ACC2_DECL() unsigned long long acc2[4][2] = {{0ull,0ull},{0ull,0ull},{0ull,0ull},{0ull,0ull}}
#define FMA2_ROWS(a, wp) do {                                              \
    unsigned long long ab_;                                                 \
    ab_ = pack2(a.x, a.x); ffma2(acc2[0][0], ab_, wp.x); ffma2(acc2[0][1], ab_, wp.y); \
    ab_ = pack2(a.y, a.y); ffma2(acc2[1][0], ab_, wp.x); ffma2(acc2[1][1], ab_, wp.y); \
    ab_ = pack2(a.z, a.z); ffma2(acc2[2][0], ab_, wp.x); ffma2(acc2[2][1], ab_, wp.y); \
    ab_ = pack2(a.w, a.w); ffma2(acc2[3][0], ab_, wp.x); ffma2(acc2[3][1], ab_, wp.y); \
} while (0)

// ---------------- generic 64x64 partial GEMM (one half-block) ----------------
// out[batch 0..63][c0col..c0col+63] (+)= X[m][xk0 .. xk0+nkt*32] @ W[wk0+..][c0col+..]
__device__ __forceinline__ void gemm64(
    int half, int htid,
    const float* __restrict__ X, int ldx, int xk0,
    const float* __restrict__ W, int ldw, int wk0,
    int c0col, int nkt, float* __restrict__ outp, int ldo,
    float* xs, float* ws)
{
    const int cg = htid & 15, bg = htid >> 4;
    const int kkx = htid & 31, mx = htid >> 5;
    const int cw = htid & 63, kw = htid >> 6;
    float rx[8], rw[8];
    ACC2_DECL();
    #pragma unroll
    for (int r = 0; r < 8; r++)
        rx[r] = X[(size_t)(mx + 8*r) * ldx + xk0 + kkx];
    #pragma unroll
    for (int r = 0; r < 8; r++)
        rw[r] = W[(size_t)(wk0 + kw + 4*r) * ldw + c0col + cw];
    for (int kt = 0; kt < nkt; kt++) {
        #pragma unroll
        for (int r = 0; r < 8; r++) {
            xs[kkx*68 + mx + 8*r] = rx[r];
            ws[(kw + 4*r)*68 + cw] = rw[r];
        }
        hbar(half);
        if (kt + 1 < nkt) {
            int k0 = (kt + 1) * 32;
            #pragma unroll
            for (int r = 0; r < 8; r++)
                rx[r] = X[(size_t)(mx + 8*r) * ldx + xk0 + k0 + kkx];
            #pragma unroll
            for (int r = 0; r < 8; r++)
                rw[r] = W[(size_t)(wk0 + k0 + kw + 4*r) * ldw + c0col + cw];
        }
        #pragma unroll
        for (int kk = 0; kk < 32; kk++) {
            float4 a = *(const float4*)&xs[kk*68 + bg * 4];
            ulonglong2 wp = *(const ulonglong2*)&ws[kk*68 + cg * 4];
            FMA2_ROWS(a, wp);
        }
        hbar(half);
    }
    #pragma unroll
    for (int i = 0; i < 4; i++) {
        float2 lo = unpack2(acc2[i][0]), hi = unpack2(acc2[i][1]);
        float4 r = make_float4(lo.x, lo.y, hi.x, hi.y);
        *(float4*)&outp[(size_t)(bg*4 + i) * ldo + c0col + cg*4] = r;
    }
}

// ---------------- logits for one batch (one half-block, 256 threads) -------
__device__ __forceinline__ void do_logits(int b, int tt, float* arena, int htid,
                                          int half, const float* __restrict__ embW,
                                          const float* __restrict__ char_b,
                                          float* __restrict__ pred)
{
    float* h2s = arena; float* ctxs = arena + 256;
    h2s[htid]  = g_h2[b * D_ + htid];
    ctxs[htid] = g_ctx[b * P_ + htid];
    hbar(half);
    int hw = htid >> 5, hl = htid & 31;
    float4 o0 = *(const float4*)&h2s[hl*4];
    float4 o1 = *(const float4*)&h2s[128 + hl*4];
    float4 o2 = *(const float4*)&ctxs[hl*4];
    float4 o3 = *(const float4*)&ctxs[128 + hl*4];
    for (int v = hw; v < V_; v += 8) {
        const float4* ev = (const float4*)(embW + (size_t)v * E_);
        float acc = dot4(o0, ev[hl]) + dot4(o1, ev[32+hl])
                  + dot4(o2, ev[64+hl]) + dot4(o3, ev[96+hl]);
        #pragma unroll
        for (int off = 16; off; off >>= 1) acc += __shfl_xor_sync(0xffffffffu, acc, off);
        if (hl == 0) pred[((size_t)b * T_ + tt) * V_ + v] = acc + char_b[v];
    }
}

// ================== the ONE kernel ==================
__global__ void __launch_bounds__(NTHR, 1)
persist_kernel(const float* __restrict__ enc,  const float* __restrict__ embW,
               const float* __restrict__ Wih1, const float* __restrict__ bih1,
               const float* __restrict__ Whh1, const float* __restrict__ bhh1,
               const float* __restrict__ Wih2, const float* __restrict__ bih2,
               const float* __restrict__ Whh2, const float* __restrict__ bhh2,
               const float* __restrict__ Wk,   const float* __restrict__ bk,
               const float* __restrict__ Wv,   const float* __restrict__ bv,
               const float* __restrict__ Wq,   const float* __restrict__ bq,
               const float* __restrict__ char_b,
               const int* __restrict__ lens,   const int* __restrict__ y,
               float* __restrict__ pred,       float* __restrict__ plot)
{
    __shared__ __align__(16) float sh[8704];
    const int tid  = threadIdx.x;
    const int bid  = blockIdx.x;
    const int half = tid >> 8;
    const int htid = tid & 255;
    const int vb   = bid * 2 + half;
    float* xs = sh + half * 4352;
    float* ws = xs + 2176;
    const int cg = htid & 15, bg = htid >> 4;
    const int w = tid >> 5, lane = tid & 31;
    const float scl = 0.0625f;

    // ============ PRE-A: folds, embg, init ============
    if (vb < 32) {
        int n0 = (vb & 3) * 64, m0 = (vb >> 2) * 64;
        ACC2_DECL();
        for (int k0 = 0; k0 < P_; k0 += 32) {
            #pragma unroll
            for (int e = htid; e < 2048; e += 256) {
                int kk = e & 31, m = e >> 5;
                xs[kk*68 + m] = Wk[(m0 + m) * P_ + k0 + kk];
            }
            #pragma unroll
            for (int e = htid; e < 2048; e += 256) {
                int kk = e & 31, h = e >> 5;
                ws[kk*68 + h] = Wq[(n0 + h) * P_ + k0 + kk];
            }
            hbar(half);
            #pragma unroll
            for (int kk = 0; kk < 32; kk++) {
                float4 a = *(const float4*)&xs[kk*68 + bg * 4];
                ulonglong2 wp = *(const ulonglong2*)&ws[kk*68 + cg * 4];
                FMA2_ROWS(a, wp);
            }
            hbar(half);
        }
        #pragma unroll
        for (int i = 0; i < 4; i++) {
            float2 lo = unpack2(acc2[i][0]), hi = unpack2(acc2[i][1]);
            float4 r = make_float4(lo.x*scl, lo.y*scl, hi.x*scl, hi.y*scl);
            *(float4*)&g_wfold[(size_t)(m0 + bg*4 + i) * D_ + n0 + cg*4] = r;
        }
    } else if (vb < 34) {
        int e = (vb - 32) * 256 + htid;
        float a = 0.f;
        for (int p = 0; p < P_; p++) a += Wk[e * P_ + p] * bq[p];
        g_wb[e] = a * scl;
    } else if (vb == 34) {
        float a = 0.f;
        for (int p = 0; p < P_; p++) a += bk[p] * Wq[htid * P_ + p];
        g_bfold[htid] = a * scl;
        if (htid == 0) {
            float c = 0.f;
            for (int p = 0; p < P_; p++) c += bk[p] * bq[p];
            g_c0[0] = c * scl;
        }
    } else if (vb < 65) {
        int v = vb - 35;
        float* es = xs;
        es[htid] = embW[v * E_ + htid];
        es[htid + 256] = embW[v * E_ + 256 + htid];
        hbar(half);
        float acc[8];
        #pragma unroll
        for (int r = 0; r < 8; r++) {
            int g = htid + 256 * r;
            acc[r] = bih1[g] + bhh1[g];
        }
        for (int e = 0; e < E_; e++) {
            float ev = es[e];
            const float* wr = Wih1 + (size_t)e * G1 + htid;
            #pragma unroll
            for (int r = 0; r < 8; r++) acc[r] += ev * wr[256 * r];
        }
        #pragma unroll
        for (int r = 0; r < 8; r++) g_embg[v * G1 + htid + 256 * r] = acc[r];
    } else if (vb < 129) {
        // zero h1-part partials (h1(−1)=0)
        int idx = vb - 65;
        float* gz = &g_gp1[4][0];
        for (int j = htid; j < 8192; j += 256) gz[(size_t)idx * 8192 + j] = 0.f;
    } else if (vb >= 192) {
        int b = vb - 192;
        for (int j = htid; j < H_; j += 256) { g_h1[b*H_ + j] = 0.f; g_c1[b*H_ + j] = 0.f; }
        g_h2[b*D_ + htid] = 0.f; g_c2[b*D_ + htid] = 0.f;
        float* es = xs;
        es[htid] = enc[(size_t)b * S_ * ENC_ + htid];
        es[htid + 256] = enc[(size_t)b * S_ * ENC_ + 256 + htid];
        hbar(half);
        float acc = bk[htid];
        #pragma unroll 4
        for (int k = 0; k < ENC_; k++) acc += es[k] * Wk[k * P_ + htid];
        g_ctx[b*P_ + htid] = acc;
    }
    gbar();

    // ============ PRE-B: main GEMM (fp16 out) + kbq ============
    {
        for (int q = 0; q < 25; q++) {
            int tt = vb + 256 * q;
            int n0 = (tt & 7) * 64, m0 = (tt >> 3) * 64;
            bool isval = (n0 < P_);
            const float* __restrict__ Bsrc = isval ? (Wv + n0) : (g_wfold + (n0 - P_));
            ACC2_DECL();
            for (int k0 = 0; k0 < ENC_; k0 += 32) {
                #pragma unroll
                for (int e = htid; e < 2048; e += 256) {
                    int kk = e & 31, m = e >> 5;
                    xs[kk*68 + m] = enc[(size_t)(m0 + m) * ENC_ + k0 + kk];
                }
                #pragma unroll
                for (int e = htid; e < 2048; e += 256) {
                    int c = e & 63, kk = e >> 6;
                    ws[kk*68 + c] = Bsrc[(size_t)(k0 + kk) * P_ + c];
                }
                hbar(half);
                #pragma unroll
                for (int kk = 0; kk < 32; kk++) {
                    float4 a = *(const float4*)&xs[kk*68 + bg * 4];
                    ulonglong2 wp = *(const ulonglong2*)&ws[kk*68 + cg * 4];
                    FMA2_ROWS(a, wp);
                }
                hbar(half);
            }
            float4 bias = isval ? *(const float4*)&bv[n0 + cg*4]
                                : *(const float4*)&g_bfold[n0 - P_ + cg*4];
            __half2* o2 = (__half2*)(isval ? g_valh : g_keyqh);
            int colbase = isval ? n0 : (n0 - P_);
            #pragma unroll
            for (int i = 0; i < 4; i++) {
                float2 lo = unpack2(acc2[i][0]), hi = unpack2(acc2[i][1]);
                int rowc = (m0 + bg*4 + i) * P_ + colbase + cg*4;
                o2[(rowc >> 1)    ] = __floats2half2_rn(lo.x + bias.x, lo.y + bias.y);
                o2[(rowc >> 1) + 1] = __floats2half2_rn(hi.x + bias.z, hi.y + bias.w);
            }
        }
        hbar(half);
        float* wbs = xs;
        wbs[htid] = g_wb[htid]; wbs[256 + htid] = g_wb[256 + htid];
        hbar(half);
        int hl = htid & 31, hw = htid >> 5;
        float4 w0 = *(const float4*)&wbs[hl*4];
        float4 w1 = *(const float4*)&wbs[128 + hl*4];
        float4 w2 = *(const float4*)&wbs[256 + hl*4];
        float4 w3 = *(const float4*)&wbs[384 + hl*4];
        float c0 = g_c0[0];
        int r0 = vb * 200 + hw * 25;
        for (int i = 0; i < 25; i++) {
            int row = r0 + i;
            const float4* ep = (const float4*)(enc + (size_t)row * ENC_);
            float acc = dot4(ep[hl], w0) + dot4(ep[32+hl], w1)
                      + dot4(ep[64+hl], w2) + dot4(ep[96+hl], w3);
            #pragma unroll
            for (int off = 16; off; off >>= 1) acc += __shfl_xor_sync(0xffffffffu, acc, off);
            if (hl == 0) g_kbq[row] = acc + c0;
        }
    }
    gbar();

    // ============ DECODE LOOP ============
    for (int t = 0; t < T_; t++) {
        // ---- A: ctx(t-1)@Wihc -> gp1[0..3] | logits(t-1) | h2(t-1)@Whh2 -> gp2[8..11]
        if (bid < 64) {
            int vh = bid * 2 + half;
            int ct = vh >> 2, ks = vh & 3;
            gemm64(half, htid, g_ctx, P_, ks*64, Wih1, G1, E_ + ks*64,
                   ct*64, 2, g_gp1[ks], G1, xs, ws);
        } else if (bid < 96) {
            if (t > 0) do_logits((bid - 64)*2 + half, t - 1, xs, htid, half, embW, char_b, pred);
        } else {
            int idx = (bid - 96)*2 + half;
            int ct = idx >> 2, ks = idx & 3;
            gemm64(half, htid, g_h2, D_, ks*64, Whh2, G2, ks*64,
                   ct*64, 2, g_gp2[8 + ks], G2, xs, ws);
        }
        gbar();

        // ---- B: cell1
        if (bid < 64) {
            int idx = bid * NTHR + tid;
            int b = idx >> 9, u = idx & 511;
            int tok = (t == 0) ? 0 : y[b * T_ + (t - 1)];
            float G[4];
            #pragma unroll
            for (int g = 0; g < 4; g++) {
                int col = g * H_ + u;
                float s = g_embg[tok * G1 + col];
                #pragma unroll
                for (int ks = 0; ks < 8; ks++) s += g_gp1[ks][b * G1 + col];
                G[g] = s;
            }
            float c = g_c1[idx];
            float cn = sigf(G[1]) * c + sigf(G[0]) * tanhf(G[2]);
            g_c1[idx] = cn;
            g_h1[idx] = sigf(G[3]) * tanhf(cn);
        }
        gbar();

        // ---- C: h1(t)@Wih2 -> gp2[0..7]
        if (bid < 64) {
            int vh = bid * 2 + half;
            int ct = vh >> 3, ks = vh & 7;
            gemm64(half, htid, g_h1, H_, ks*64, Wih2, G2, ks*64,
                   ct*64, 2, g_gp2[ks], G2, xs, ws);
        }
        gbar();

        // ---- D: cell2 + attention (blocks 0..63)  ||  h1(t)@Whh1 -> gp1[4..7] (blocks 64..127)
        if (bid < 64) {
            int b = bid;
            float* h2s   = sh;           // 256
            float* sc    = sh + 256;     // 800
            float* red   = sh + 1056;    // 512
            float* cpart = sh + 1568;    // 16*256 = 4096
            if (tid < 256) {
                int u = tid;
                float G[4];
                #pragma unroll
                for (int g = 0; g < 4; g++) {
                    int col = g * D_ + u;
                    float s = bih2[col] + bhh2[col];
                    #pragma unroll
                    for (int ks = 0; ks < 12; ks++) s += g_gp2[ks][b * G2 + col];
                    G[g] = s;
                }
                int idx = b * D_ + u;
                float c = g_c2[idx];
                float cn = sigf(G[1]) * c + sigf(G[0]) * tanhf(G[2]);
                g_c2[idx] = cn;
                float hn = sigf(G[3]) * tanhf(cn);
                g_h2[idx] = hn;
                h2s[u] = hn;
            }
            __syncthreads();
            int len = lens[b];
            // scores (fp16 keys): 16 warps x 50 rows
            {
                float4 qa = *(const float4*)&h2s[lane*8];
                float4 qb = *(const float4*)&h2s[lane*8 + 4];
                const uint4* kb4 = (const uint4*)(g_keyqh + (size_t)b * S_ * D_);
                const float* __restrict__ kq = g_kbq + b * S_;
                int base = w * 50, bend = base + 50;
                for (int j = 0; j < 7; j++) {
                    int s0 = base + j * 8;
                    float a0=0,a1=0,a2=0,a3=0,a4=0,a5=0,a6=0,a7=0;
                    #define SCORE1(i, ai)                                                  \
                        if (s0 + i < bend && s0 + i < len) {                               \
                            uint4 u4 = kb4[(size_t)(s0 + i) * 32 + lane];                  \
                            float2 f0 = __half22float2(((const __half2*)&u4)[0]);          \
                            float2 f1 = __half22float2(((const __half2*)&u4)[1]);          \
                            float2 f2 = __half22float2(((const __half2*)&u4)[2]);          \
                            float2 f3 = __half22float2(((const __half2*)&u4)[3]);          \
                            ai = f0.x*qa.x + f0.y*qa.y + f1.x*qa.z + f1.y*qa.w             \
                               + f2.x*qb.x + f2.y*qb.y + f3.x*qb.z + f3.y*qb.w;            \
                        }
                    SCORE1(0,a0) SCORE1(1,a1) SCORE1(2,a2) SCORE1(3,a3)
                    SCORE1(4,a4) SCORE1(5,a5) SCORE1(6,a6) SCORE1(7,a7)
                    #undef SCORE1
                    #pragma unroll
                    for (int off = 16; off; off >>= 1) {
                        a0 += __shfl_xor_sync(0xffffffffu, a0, off);
                        a1 += __shfl_xor_sync(0xffffffffu, a1, off);
                        a2 += __shfl_xor_sync(0xffffffffu, a2, off);
                        a3 += __shfl_xor_sync(0xffffffffu, a3, off);
                        a4 += __shfl_xor_sync(0xffffffffu, a4, off);
                        a5 += __shfl_xor_sync(0xffffffffu, a5, off);
                        a6 += __shfl_xor_sync(0xffffffffu, a6, off);
                        a7 += __shfl_xor_sync(0xffffffffu, a7, off);
                    }
                    if (lane < 8) {
                        int s = s0 + lane;
                        if (s < bend) {
                            float v = (lane==0)?a0:(lane==1)?a1:(lane==2)?a2:(lane==3)?a3
                                     :(lane==4)?a4:(lane==5)?a5:(lane==6)?a6:a7;
                            sc[s] = (s < len) ? v + kq[s] : -1e9f;
                        }
                    }
                }
            }
            __syncthreads();
            // softmax
            float mx2 = -3.4e38f;
            for (int s = tid; s < S_; s += NTHR) mx2 = fmaxf(mx2, sc[s]);
            red[tid] = mx2; __syncthreads();
            for (int off = 256; off; off >>= 1) { if (tid < off) red[tid] = fmaxf(red[tid], red[tid+off]); __syncthreads(); }
            float M = red[0];
            __syncthreads();
            float sm = 0.f;
            for (int s = tid; s < S_; s += NTHR) { float e = __expf(sc[s] - M); sc[s] = e; sm += e; }
            red[tid] = sm; __syncthreads();
            for (int off = 256; off; off >>= 1) { if (tid < off) red[tid] += red[tid+off]; __syncthreads(); }
            float inv = 1.f / red[0];
            __syncthreads();
            // context (fp16 values): 16 s-slices x 32 col-groups of 8
            {
                int sl = tid >> 5, cgp = tid & 31;
                const uint4* vp4 = (const uint4*)(g_valh + (size_t)b * S_ * P_) + cgp;
                float acc[8] = {0,0,0,0,0,0,0,0};
                int sbeg = sl * 50, send = sbeg + 50; if (send > len) send = len;
                for (int s = sbeg; s < send; s++) {
                    float wgt = sc[s];
                    uint4 u4 = vp4[(size_t)s * 32];
                    float2 f0 = __half22float2(((const __half2*)&u4)[0]);
                    float2 f1 = __half22float2(((const __half2*)&u4)[1]);
                    float2 f2 = __half22float2(((const __half2*)&u4)[2]);
                    float2 f3 = __half22float2(((const __half2*)&u4)[3]);
                    acc[0] += wgt*f0.x; acc[1] += wgt*f0.y; acc[2] += wgt*f1.x; acc[3] += wgt*f1.y;
                    acc[4] += wgt*f2.x; acc[5] += wgt*f2.y; acc[6] += wgt*f3.x; acc[7] += wgt*f3.y;
                }
                #pragma unroll
                for (int i = 0; i < 8; i++) cpart[sl*256 + cgp*8 + i] = acc[i];
            }
            __syncthreads();
            if (tid < 256) {
                float s = 0.f;
                #pragma unroll
                for (int i = 0; i < 16; i++) s += cpart[i*256 + tid];
                g_ctx[b * P_ + tid] = s * inv;
            }
            if (b == 0) {
                for (int s = tid; s < S_; s += NTHR) plot[s * T_ + t] = sc[s] * inv;
            }
        } else {
            int idx = (bid - 64)*2 + half;
            int ct = idx >> 2, ks = idx & 3;
            gemm64(half, htid, g_h1, H_, ks*128, Whh1, G1, ks*128,
                   ct*64, 4, g_gp1[4 + ks], G1, xs, ws);
        }
        gbar();
    }

    // ---- final logits (t = T-1) ----
    if (bid >= 64 && bid < 96) {
        do_logits((bid - 64)*2 + half, T_ - 1, xs, htid, half, embW, char_b, pred);
    }
}

// ---------------- launch: ONE node -----------------------------------------
extern "C" void kernel_launch(void* const* d_in, const int* in_sizes, int n_in,
                              void* d_out, int out_size) {
    const float* enc    = (const float*)d_in[0];
    const float* embW   = (const float*)d_in[1];
    const float* Wih1   = (const float*)d_in[2];
    const float* bih1   = (const float*)d_in[3];
    const float* Whh1   = (const float*)d_in[4];
    const float* bhh1   = (const float*)d_in[5];
    const float* Wih2   = (const float*)d_in[6];
    const float* bih2   = (const float*)d_in[7];
    const float* Whh2   = (const float*)d_in[8];
    const float* bhh2   = (const float*)d_in[9];
    const float* Wk     = (const float*)d_in[10];
    const float* bk     = (const float*)d_in[11];
    const float* Wv     = (const float*)d_in[12];
    const float* bv     = (const float*)d_in[13];
    const float* Wq     = (const float*)d_in[14];
    const float* bq     = (const float*)d_in[15];
    const float* char_b = (const float*)d_in[16];
    const int*   lens   = (const int*)d_in[17];
    const int*   y      = (const int*)d_in[18];

    float* pred = (float*)d_out;                 // (B, T, V)
    float* plot = pred + (size_t)B_ * T_ * V_;   // (S, T)

    persist_kernel<<<NBLK, NTHR>>>(enc, embW, Wih1, bih1, Whh1, bhh1,
                                   Wih2, bih2, Whh2, bhh2,
                                   Wk, bk, Wv, bv, Wq, bq,
                                   char_b, lens, y, pred, plot);
}

// round 11
// speedup vs baseline: 10.5734x; 1.0162x over previous
#include <cuda_runtime.h>
#include <cuda_fp16.h>
#include <math.h>

#define B_   64
#define S_   800
#define ENC_ 512
#define T_   250
#define V_   30
#define E_   512
#define H_   512
#define D_   256
#define P_   256
#define NBLK 128
#define NTHR 512
#define G1   (4*H_)
#define G2   (4*D_)

// ---------------- device scratch ----------------
__device__ __align__(16) __half g_valh [B_*S_*P_];   // val_proj fp16
__device__ __align__(16) __half g_keyqh[B_*S_*D_];   // folded key fp16
__device__ float g_kbq [B_*S_];
__device__ float g_embg[V_*G1];
__device__ float g_wfold[ENC_*D_];
__device__ float g_bfold[D_];
__device__ float g_wb[ENC_];
__device__ float g_c0[1];
__device__ float g_h1[B_*H_];
__device__ float g_c1[B_*H_];
__device__ float g_h2[B_*D_];
__device__ float g_c2[B_*D_];
__device__ float g_ctx[B_*P_];
__device__ float g_gp1[12][B_*G1];   // 0..3 ctx-part (A); 4..11 h1-part (C: cols<1024, D: cols>=1024)
__device__ float g_gp2[12][B_*G2];   // 0..7 Wih2 (C), 8..11 Whh2 (A)

// ---------------- distributed grid barrier ----------------
__device__ int g_arr[NBLK];          // zero-init; monotonic generation per block
__device__ int g_rel;                // zero-init; released generation

__device__ __forceinline__ void gbar(int& gen) {
    gen++;
    __syncthreads();
    if (blockIdx.x == 0) {
        if (threadIdx.x == 0) {
            __threadfence();
            *(volatile int*)&g_arr[0] = gen;
        }
        if (threadIdx.x < NBLK) {
            while (*(volatile int*)&g_arr[threadIdx.x] < gen) { }
        }
        __syncthreads();
        if (threadIdx.x == 0) {
            *(volatile int*)&g_rel = gen;
            __threadfence();           // also invalidates this SM's L1
        }
        __syncthreads();
    } else {
        if (threadIdx.x == 0) {
            __threadfence();
            *(volatile int*)&g_arr[blockIdx.x] = gen;
            while (*(volatile int*)&g_rel < gen) { }
            __threadfence();           // acquire + L1 invalidate
        }
        __syncthreads();
    }
}

__device__ __forceinline__ void hbar(int half) {
    asm volatile("bar.sync %0, 256;" :: "r"(half + 1) : "memory");
}

__device__ __forceinline__ float sigf(float x) { return 1.0f / (1.0f + expf(-x)); }
__device__ __forceinline__ float dot4(float4 a, float4 b) {
    return a.x*b.x + a.y*b.y + a.z*b.z + a.w*b.w;
}

// ---------------- packed fp32x2 FMA ----------------
__device__ __forceinline__ unsigned long long pack2(float x, float y) {
    unsigned long long r; asm("mov.b64 %0, {%1, %2};" : "=l"(r) : "f"(x), "f"(y)); return r;
}
__device__ __forceinline__ float2 unpack2(unsigned long long v) {
    float2 f; asm("mov.b64 {%0, %1}, %2;" : "=f"(f.x), "=f"(f.y) : "l"(v)); return f;
}
__device__ __forceinline__ void ffma2(unsigned long long& acc, unsigned long long a, unsigned long long b) {
    asm("fma.rn.f32x2 %0, %1, %2, %0;" : "+l"(acc) : "l"(a), "l"(b));
}

#define ACC2_DECL() unsigned long long acc2[4][2] = {{0ull,0ull},{0ull,0ull},{0ull,0ull},{0ull,0ull}}
#define FMA2_ROWS(a, wp) do {                                              \
    unsigned long long ab_;                                                 \
    ab_ = pack2(a.x, a.x); ffma2(acc2[0][0], ab_, wp.x); ffma2(acc2[0][1], ab_, wp.y); \
    ab_ = pack2(a.y, a.y); ffma2(acc2[1][0], ab_, wp.x); ffma2(acc2[1][1], ab_, wp.y); \
    ab_ = pack2(a.z, a.z); ffma2(acc2[2][0], ab_, wp.x); ffma2(acc2[2][1], ab_, wp.y); \
    ab_ = pack2(a.w, a.w); ffma2(acc2[3][0], ab_, wp.x); ffma2(acc2[3][1], ab_, wp.y); \
} while (0)

// ---------------- generic 64x64 partial GEMM (one half-block) ----------------
__device__ __forceinline__ void gemm64(
    int half, int htid,
    const float* __restrict__ X, int ldx, int xk0,
    const float* __restrict__ W, int ldw, int wk0,
    int c0col, int nkt, float* __restrict__ outp, int ldo,
    float* xs, float* ws)
{
    const int cg = htid & 15, bg = htid >> 4;
    const int kkx = htid & 31, mx = htid >> 5;
    const int cw = htid & 63, kw = htid >> 6;
    float rx[8], rw[8];
    ACC2_DECL();
    #pragma unroll
    for (int r = 0; r < 8; r++)
        rx[r] = X[(size_t)(mx + 8*r) * ldx + xk0 + kkx];
    #pragma unroll
    for (int r = 0; r < 8; r++)
        rw[r] = W[(size_t)(wk0 + kw + 4*r) * ldw + c0col + cw];
    for (int kt = 0; kt < nkt; kt++) {
        #pragma unroll
        for (int r = 0; r < 8; r++) {
            xs[kkx*68 + mx + 8*r] = rx[r];
            ws[(kw + 4*r)*68 + cw] = rw[r];
        }
        hbar(half);
        if (kt + 1 < nkt) {
            int k0 = (kt + 1) * 32;
            #pragma unroll
            for (int r = 0; r < 8; r++)
                rx[r] = X[(size_t)(mx + 8*r) * ldx + xk0 + k0 + kkx];
            #pragma unroll
            for (int r = 0; r < 8; r++)
                rw[r] = W[(size_t)(wk0 + k0 + kw + 4*r) * ldw + c0col + cw];
        }
        #pragma unroll
        for (int kk = 0; kk < 32; kk++) {
            float4 a = *(const float4*)&xs[kk*68 + bg * 4];
            ulonglong2 wp = *(const ulonglong2*)&ws[kk*68 + cg * 4];
            FMA2_ROWS(a, wp);
        }
        hbar(half);
    }
    #pragma unroll
    for (int i = 0; i < 4; i++) {
        float2 lo = unpack2(acc2[i][0]), hi = unpack2(acc2[i][1]);
        float4 r = make_float4(lo.x, lo.y, hi.x, hi.y);
        *(float4*)&outp[(size_t)(bg*4 + i) * ldo + c0col + cg*4] = r;
    }
}

// ---------------- logits for one batch (one half-block) ----------------
__device__ __forceinline__ void do_logits(int b, int tt, float* arena, int htid,
                                          int half, const float* __restrict__ embW,
                                          const float* __restrict__ char_b,
                                          float* __restrict__ pred)
{
    float* h2s = arena; float* ctxs = arena + 256;
    h2s[htid]  = g_h2[b * D_ + htid];
    ctxs[htid] = g_ctx[b * P_ + htid];
    hbar(half);
    int hw = htid >> 5, hl = htid & 31;
    float4 o0 = *(const float4*)&h2s[hl*4];
    float4 o1 = *(const float4*)&h2s[128 + hl*4];
    float4 o2 = *(const float4*)&ctxs[hl*4];
    float4 o3 = *(const float4*)&ctxs[128 + hl*4];
    for (int v = hw; v < V_; v += 8) {
        const float4* ev = (const float4*)(embW + (size_t)v * E_);
        float acc = dot4(o0, ev[hl]) + dot4(o1, ev[32+hl])
                  + dot4(o2, ev[64+hl]) + dot4(o3, ev[96+hl]);
        #pragma unroll
        for (int off = 16; off; off >>= 1) acc += __shfl_xor_sync(0xffffffffu, acc, off);
        if (hl == 0) pred[((size_t)b * T_ + tt) * V_ + v] = acc + char_b[v];
    }
}

// ================== the ONE kernel ==================
__global__ void __launch_bounds__(NTHR, 1)
persist_kernel(const float* __restrict__ enc,  const float* __restrict__ embW,
               const float* __restrict__ Wih1, const float* __restrict__ bih1,
               const float* __restrict__ Whh1, const float* __restrict__ bhh1,
               const float* __restrict__ Wih2, const float* __restrict__ bih2,
               const float* __restrict__ Whh2, const float* __restrict__ bhh2,
               const float* __restrict__ Wk,   const float* __restrict__ bk,
               const float* __restrict__ Wv,   const float* __restrict__ bv,
               const float* __restrict__ Wq,   const float* __restrict__ bq,
               const float* __restrict__ char_b,
               const int* __restrict__ lens,   const int* __restrict__ y,
               float* __restrict__ pred,       float* __restrict__ plot)
{
    __shared__ __align__(16) float sh[8704];
    const int tid  = threadIdx.x;
    const int bid  = blockIdx.x;
    const int half = tid >> 8;
    const int htid = tid & 255;
    const int vb   = bid * 2 + half;
    float* xs = sh + half * 4352;
    float* ws = xs + 2176;
    const int cg = htid & 15, bg = htid >> 4;
    const int w = tid >> 5, lane = tid & 31;
    const float scl = 0.0625f;

    int gen = *(volatile int*)&g_rel;   // carries across graph replays

    // ============ PRE-A: folds, embg, init ============
    if (vb < 32) {
        int n0 = (vb & 3) * 64, m0 = (vb >> 2) * 64;
        ACC2_DECL();
        for (int k0 = 0; k0 < P_; k0 += 32) {
            #pragma unroll
            for (int e = htid; e < 2048; e += 256) {
                int kk = e & 31, m = e >> 5;
                xs[kk*68 + m] = Wk[(m0 + m) * P_ + k0 + kk];
            }
            #pragma unroll
            for (int e = htid; e < 2048; e += 256) {
                int kk = e & 31, h = e >> 5;
                ws[kk*68 + h] = Wq[(n0 + h) * P_ + k0 + kk];
            }
            hbar(half);
            #pragma unroll
            for (int kk = 0; kk < 32; kk++) {
                float4 a = *(const float4*)&xs[kk*68 + bg * 4];
                ulonglong2 wp = *(const ulonglong2*)&ws[kk*68 + cg * 4];
                FMA2_ROWS(a, wp);
            }
            hbar(half);
        }
        #pragma unroll
        for (int i = 0; i < 4; i++) {
            float2 lo = unpack2(acc2[i][0]), hi = unpack2(acc2[i][1]);
            float4 r = make_float4(lo.x*scl, lo.y*scl, hi.x*scl, hi.y*scl);
            *(float4*)&g_wfold[(size_t)(m0 + bg*4 + i) * D_ + n0 + cg*4] = r;
        }
    } else if (vb < 34) {
        int e = (vb - 32) * 256 + htid;
        float a = 0.f;
        for (int p = 0; p < P_; p++) a += Wk[e * P_ + p] * bq[p];
        g_wb[e] = a * scl;
    } else if (vb == 34) {
        float a = 0.f;
        for (int p = 0; p < P_; p++) a += bk[p] * Wq[htid * P_ + p];
        g_bfold[htid] = a * scl;
        if (htid == 0) {
            float c = 0.f;
            for (int p = 0; p < P_; p++) c += bk[p] * bq[p];
            g_c0[0] = c * scl;
        }
    } else if (vb < 65) {
        int v = vb - 35;
        float* es = xs;
        es[htid] = embW[v * E_ + htid];
        es[htid + 256] = embW[v * E_ + 256 + htid];
        hbar(half);
        float acc[8];
        #pragma unroll
        for (int r = 0; r < 8; r++) {
            int g = htid + 256 * r;
            acc[r] = bih1[g] + bhh1[g];
        }
        for (int e = 0; e < E_; e++) {
            float ev = es[e];
            const float* wr = Wih1 + (size_t)e * G1 + htid;
            #pragma unroll
            for (int r = 0; r < 8; r++) acc[r] += ev * wr[256 * r];
        }
        #pragma unroll
        for (int r = 0; r < 8; r++) g_embg[v * G1 + htid + 256 * r] = acc[r];
    } else if (vb < 129) {
        // zero 8 h1-part partial slices (h1(-1) = 0): slices 4..11
        int idx = vb - 65;                       // 0..63
        float* gz = &g_gp1[4][0];
        for (int j = htid; j < 16384; j += 256)
            gz[(size_t)idx * 16384 + j] = 0.f;
    } else if (vb >= 192) {
        int b = vb - 192;
        for (int j = htid; j < H_; j += 256) { g_h1[b*H_ + j] = 0.f; g_c1[b*H_ + j] = 0.f; }
        g_h2[b*D_ + htid] = 0.f; g_c2[b*D_ + htid] = 0.f;
        float* es = xs;
        es[htid] = enc[(size_t)b * S_ * ENC_ + htid];
        es[htid + 256] = enc[(size_t)b * S_ * ENC_ + 256 + htid];
        hbar(half);
        float acc = bk[htid];
        #pragma unroll 4
        for (int k = 0; k < ENC_; k++) acc += es[k] * Wk[k * P_ + htid];
        g_ctx[b*P_ + htid] = acc;
    }
    gbar(gen);

    // ============ PRE-B: main GEMM (fp16 out) + kbq ============
    {
        for (int q = 0; q < 25; q++) {
            int tt = vb + 256 * q;
            int n0 = (tt & 7) * 64, m0 = (tt >> 3) * 64;
            bool isval = (n0 < P_);
            const float* __restrict__ Bsrc = isval ? (Wv + n0) : (g_wfold + (n0 - P_));
            ACC2_DECL();
            for (int k0 = 0; k0 < ENC_; k0 += 32) {
                #pragma unroll
                for (int e = htid; e < 2048; e += 256) {
                    int kk = e & 31, m = e >> 5;
                    xs[kk*68 + m] = enc[(size_t)(m0 + m) * ENC_ + k0 + kk];
                }
                #pragma unroll
                for (int e = htid; e < 2048; e += 256) {
                    int c = e & 63, kk = e >> 6;
                    ws[kk*68 + c] = Bsrc[(size_t)(k0 + kk) * P_ + c];
                }
                hbar(half);
                #pragma unroll
                for (int kk = 0; kk < 32; kk++) {
                    float4 a = *(const float4*)&xs[kk*68 + bg * 4];
                    ulonglong2 wp = *(const ulonglong2*)&ws[kk*68 + cg * 4];
                    FMA2_ROWS(a, wp);
                }
                hbar(half);
            }
            float4 bias = isval ? *(const float4*)&bv[n0 + cg*4]
                                : *(const float4*)&g_bfold[n0 - P_ + cg*4];
            __half2* o2 = (__half2*)(isval ? g_valh : g_keyqh);
            int colbase = isval ? n0 : (n0 - P_);
            #pragma unroll
            for (int i = 0; i < 4; i++) {
                float2 lo = unpack2(acc2[i][0]), hi = unpack2(acc2[i][1]);
                int rowc = (m0 + bg*4 + i) * P_ + colbase + cg*4;
                o2[(rowc >> 1)    ] = __floats2half2_rn(lo.x + bias.x, lo.y + bias.y);
                o2[(rowc >> 1) + 1] = __floats2half2_rn(hi.x + bias.z, hi.y + bias.w);
            }
        }
        hbar(half);
        float* wbs = xs;
        wbs[htid] = g_wb[htid]; wbs[256 + htid] = g_wb[256 + htid];
        hbar(half);
        int hl = htid & 31, hw = htid >> 5;
        float4 w0 = *(const float4*)&wbs[hl*4];
        float4 w1 = *(const float4*)&wbs[128 + hl*4];
        float4 w2 = *(const float4*)&wbs[256 + hl*4];
        float4 w3 = *(const float4*)&wbs[384 + hl*4];
        float c0 = g_c0[0];
        int r0 = vb * 200 + hw * 25;
        for (int i = 0; i < 25; i++) {
            int row = r0 + i;
            const float4* ep = (const float4*)(enc + (size_t)row * ENC_);
            float acc = dot4(ep[hl], w0) + dot4(ep[32+hl], w1)
                      + dot4(ep[64+hl], w2) + dot4(ep[96+hl], w3);
            #pragma unroll
            for (int off = 16; off; off >>= 1) acc += __shfl_xor_sync(0xffffffffu, acc, off);
            if (hl == 0) g_kbq[row] = acc + c0;
        }
    }
    gbar(gen);

    // ============ DECODE LOOP (4 barriers/step) ============
    for (int t = 0; t < T_; t++) {
        // ---- A: ctx(t-1)@Wihc -> gp1[0..3] | logits(t-1) | h2(t-1)@Whh2 -> gp2[8..11]
        if (bid < 64) {
            int vh = bid * 2 + half;
            int ct = vh >> 2, ks = vh & 3;
            gemm64(half, htid, g_ctx, P_, ks*64, Wih1, G1, E_ + ks*64,
                   ct*64, 2, g_gp1[ks], G1, xs, ws);
        } else if (bid < 96) {
            if (t > 0) do_logits((bid - 64)*2 + half, t - 1, xs, htid, half, embW, char_b, pred);
        } else {
            int idx = (bid - 96)*2 + half;
            int ct = idx >> 2, ks = idx & 3;
            gemm64(half, htid, g_h2, D_, ks*64, Whh2, G2, ks*64,
                   ct*64, 2, g_gp2[8 + ks], G2, xs, ws);
        }
        gbar(gen);

        // ---- B: cell1 on all 128 blocks (gate pairs split across halves)
        {
            int e = bid * 256 + htid;            // 32768 elements
            int b = e >> 9, u = e & 511;
            int tok = (t == 0) ? 0 : y[b * T_ + (t - 1)];
            int c0 = (half*2) * H_ + u, c1 = (half*2 + 1) * H_ + u;
            float Gx = g_embg[tok*G1 + c0];
            float Gy = g_embg[tok*G1 + c1];
            #pragma unroll
            for (int ks = 0; ks < 12; ks++) {
                Gx += g_gp1[ks][b*G1 + c0];
                Gy += g_gp1[ks][b*G1 + c1];
            }
            if (half == 1) { sh[htid] = Gx; sh[256 + htid] = Gy; }
            __syncthreads();
            if (half == 0) {
                float Gi = Gx, Gf = Gy, Gg = sh[htid], Go = sh[256 + htid];
                float c = g_c1[e];
                float cn = sigf(Gf) * c + sigf(Gi) * tanhf(Gg);
                g_c1[e] = cn;
                g_h1[e] = sigf(Go) * tanhf(cn);
            }
        }
        gbar(gen);

        // ---- C: h1@Whh1 (cols 0..1023) -> gp1[4..11]  |  h1@Wih2 -> gp2[0..7]
        if (bid < 64) {
            int vh = bid * 2 + half;             // 0..127
            int ct = vh >> 3, ks = vh & 7;       // cols 0..1023, K=64 slices
            gemm64(half, htid, g_h1, H_, ks*64, Whh1, G1, ks*64,
                   ct*64, 2, g_gp1[4 + ks], G1, xs, ws);
        } else {
            int idx = (bid - 64)*2 + half;       // 0..127
            int ct = idx >> 3, ks = idx & 7;
            gemm64(half, htid, g_h1, H_, ks*64, Wih2, G2, ks*64,
                   ct*64, 2, g_gp2[ks], G2, xs, ws);
        }
        gbar(gen);

        // ---- D: cell2 + attention (blocks 0..63) | h1@Whh1 (cols 1024..2047) (blocks 64..127)
        if (bid < 64) {
            int b = bid;
            float* h2s   = sh;           // 256
            float* sc    = sh + 256;     // 800
            float* red   = sh + 1056;    // 512
            float* cpart = sh + 1568;    // 16*256
            if (tid < 256) {
                int u = tid;
                float G[4];
                #pragma unroll
                for (int g = 0; g < 4; g++) {
                    int col = g * D_ + u;
                    float s = bih2[col] + bhh2[col];
                    #pragma unroll
                    for (int ks = 0; ks < 12; ks++) s += g_gp2[ks][b * G2 + col];
                    G[g] = s;
                }
                int idx = b * D_ + u;
                float c = g_c2[idx];
                float cn = sigf(G[1]) * c + sigf(G[0]) * tanhf(G[2]);
                g_c2[idx] = cn;
                float hn = sigf(G[3]) * tanhf(cn);
                g_h2[idx] = hn;
                h2s[u] = hn;
            }
            __syncthreads();
            int len = lens[b];
            // scores (fp16 keys): 16 warps x 50 rows
            {
                float4 qa = *(const float4*)&h2s[lane*8];
                float4 qb = *(const float4*)&h2s[lane*8 + 4];
                const uint4* kb4 = (const uint4*)(g_keyqh + (size_t)b * S_ * D_);
                const float* __restrict__ kq = g_kbq + b * S_;
                int base = w * 50, bend = base + 50;
                for (int j = 0; j < 7; j++) {
                    int s0 = base + j * 8;
                    float a0=0,a1=0,a2=0,a3=0,a4=0,a5=0,a6=0,a7=0;
                    #define SCORE1(i, ai)                                                  \
                        if (s0 + i < bend && s0 + i < len) {                               \
                            uint4 u4 = kb4[(size_t)(s0 + i) * 32 + lane];                  \
                            float2 f0 = __half22float2(((const __half2*)&u4)[0]);          \
                            float2 f1 = __half22float2(((const __half2*)&u4)[1]);          \
                            float2 f2 = __half22float2(((const __half2*)&u4)[2]);          \
                            float2 f3 = __half22float2(((const __half2*)&u4)[3]);          \
                            ai = f0.x*qa.x + f0.y*qa.y + f1.x*qa.z + f1.y*qa.w             \
                               + f2.x*qb.x + f2.y*qb.y + f3.x*qb.z + f3.y*qb.w;            \
                        }
                    SCORE1(0,a0) SCORE1(1,a1) SCORE1(2,a2) SCORE1(3,a3)
                    SCORE1(4,a4) SCORE1(5,a5) SCORE1(6,a6) SCORE1(7,a7)
                    #undef SCORE1
                    #pragma unroll
                    for (int off = 16; off; off >>= 1) {
                        a0 += __shfl_xor_sync(0xffffffffu, a0, off);
                        a1 += __shfl_xor_sync(0xffffffffu, a1, off);
                        a2 += __shfl_xor_sync(0xffffffffu, a2, off);
                        a3 += __shfl_xor_sync(0xffffffffu, a3, off);
                        a4 += __shfl_xor_sync(0xffffffffu, a4, off);
                        a5 += __shfl_xor_sync(0xffffffffu, a5, off);
                        a6 += __shfl_xor_sync(0xffffffffu, a6, off);
                        a7 += __shfl_xor_sync(0xffffffffu, a7, off);
                    }
                    if (lane < 8) {
                        int s = s0 + lane;
                        if (s < bend) {
                            float v = (lane==0)?a0:(lane==1)?a1:(lane==2)?a2:(lane==3)?a3
                                     :(lane==4)?a4:(lane==5)?a5:(lane==6)?a6:a7;
                            sc[s] = (s < len) ? v + kq[s] : -1e9f;
                        }
                    }
                }
            }
            __syncthreads();
            // softmax
            float mx2 = -3.4e38f;
            for (int s = tid; s < S_; s += NTHR) mx2 = fmaxf(mx2, sc[s]);
            red[tid] = mx2; __syncthreads();
            for (int off = 256; off; off >>= 1) { if (tid < off) red[tid] = fmaxf(red[tid], red[tid+off]); __syncthreads(); }
            float M = red[0];
            __syncthreads();
            float sm = 0.f;
            for (int s = tid; s < S_; s += NTHR) { float e = __expf(sc[s] - M); sc[s] = e; sm += e; }
            red[tid] = sm; __syncthreads();
            for (int off = 256; off; off >>= 1) { if (tid < off) red[tid] += red[tid+off]; __syncthreads(); }
            float inv = 1.f / red[0];
            __syncthreads();
            // context (fp16 values)
            {
                int sl = tid >> 5, cgp = tid & 31;
                const uint4* vp4 = (const uint4*)(g_valh + (size_t)b * S_ * P_) + cgp;
                float acc[8] = {0,0,0,0,0,0,0,0};
                int sbeg = sl * 50, send = sbeg + 50; if (send > len) send = len;
                for (int s = sbeg; s < send; s++) {
                    float wgt = sc[s];
                    uint4 u4 = vp4[(size_t)s * 32];
                    float2 f0 = __half22float2(((const __half2*)&u4)[0]);
                    float2 f1 = __half22float2(((const __half2*)&u4)[1]);
                    float2 f2 = __half22float2(((const __half2*)&u4)[2]);
                    float2 f3 = __half22float2(((const __half2*)&u4)[3]);
                    acc[0] += wgt*f0.x; acc[1] += wgt*f0.y; acc[2] += wgt*f1.x; acc[3] += wgt*f1.y;
                    acc[4] += wgt*f2.x; acc[5] += wgt*f2.y; acc[6] += wgt*f3.x; acc[7] += wgt*f3.y;
                }
                #pragma unroll
                for (int i = 0; i < 8; i++) cpart[sl*256 + cgp*8 + i] = acc[i];
            }
            __syncthreads();
            if (tid < 256) {
                float s = 0.f;
                #pragma unroll
                for (int i = 0; i < 16; i++) s += cpart[i*256 + tid];
                g_ctx[b * P_ + tid] = s * inv;
            }
            if (b == 0) {
                for (int s = tid; s < S_; s += NTHR) plot[s * T_ + t] = sc[s] * inv;
            }
        } else {
            int idx = (bid - 64)*2 + half;       // 0..127
            int ct = 16 + (idx >> 3), ks = idx & 7;   // cols 1024..2047
            gemm64(half, htid, g_h1, H_, ks*64, Whh1, G1, ks*64,
                   ct*64, 2, g_gp1[4 + ks], G1, xs, ws);
        }
        gbar(gen);
    }

    // ---- final logits (t = T-1) ----
    if (bid >= 64 && bid < 96) {
        do_logits((bid - 64)*2 + half, T_ - 1, xs, htid, half, embW, char_b, pred);
    }
}

// ---------------- launch: ONE node -----------------------------------------
extern "C" void kernel_launch(void* const* d_in, const int* in_sizes, int n_in,
                              void* d_out, int out_size) {
    const float* enc    = (const float*)d_in[0];
    const float* embW   = (const float*)d_in[1];
    const float* Wih1   = (const float*)d_in[2];
    const float* bih1   = (const float*)d_in[3];
    const float* Whh1   = (const float*)d_in[4];
    const float* bhh1   = (const float*)d_in[5];
    const float* Wih2   = (const float*)d_in[6];
    const float* bih2   = (const float*)d_in[7];
    const float* Whh2   = (const float*)d_in[8];
    const float* bhh2   = (const float*)d_in[9];
    const float* Wk     = (const float*)d_in[10];
    const float* bk     = (const float*)d_in[11];
    const float* Wv     = (const float*)d_in[12];
    const float* bv     = (const float*)d_in[13];
    const float* Wq     = (const float*)d_in[14];
    const float* bq     = (const float*)d_in[15];
    const float* char_b = (const float*)d_in[16];
    const int*   lens   = (const int*)d_in[17];
    const int*   y      = (const int*)d_in[18];

    float* pred = (float*)d_out;                 // (B, T, V)
    float* plot = pred + (size_t)B_ * T_ * V_;   // (S, T)

    persist_kernel<<<NBLK, NTHR>>>(enc, embW, Wih1, bih1, Whh1, bhh1,
                                   Wih2, bih2, Whh2, bhh2,
                                   Wk, bk, Wv, bv, Wq, bq,
                                   char_b, lens, y, pred, plot);
}